// round 12
// baseline (speedup 1.0000x reference)
#include <cuda_runtime.h>
#include <cuda_bf16.h>
#include <math.h>
#include <stdint.h>

#define N_NODES  50000
#define N_EDGES  600000
#define NF       128
#define N_GRAPHS 256
#define DIM      95
#define N_OUT    12
#define N_ITERS  10
#define BN_EPS   1e-5f
#define SCAN_NBLK 196
#define NTILES   391             // ceil(50000/128)

// ---------------- scratch (zero-initialized at load; self-cleaning) --------
__device__ unsigned g_ahi[N_NODES * 64];   // bf16x2 packed: (x+agg) hi
__device__ unsigned g_alo[N_NODES * 64];
__device__ int   g_counts[N_NODES];        // zeroed by scanAB after use
__device__ int   g_offsets[N_NODES + 1];   // block-local prefixes
__device__ int   g_cursor[N_NODES];
__device__ int   g_srcidx[N_EDGES];
__device__ int   g_bsums[SCAN_NBLK];
__device__ int   g_bpre[SCAN_NBLK];
__device__ float g_stats[2 * NF];          // zeroed by recur last block
__device__ float g_gsum[N_GRAPHS * NF];    // zeroed by its recur block
__device__ int   g_tickA;                  // self-resetting tickets
__device__ int   g_tickR;

// ---------------- helpers ----------------
__device__ __forceinline__ uint32_t smem_u32(const void* p) {
    uint32_t a;
    asm("{ .reg .u64 t; cvta.to.shared.u64 t, %1; cvt.u32.u64 %0, t; }" : "=r"(a) : "l"(p));
    return a;
}
__device__ __forceinline__ void split_bf(float v, unsigned short& h, unsigned short& l) {
    __nv_bfloat16 hb = __float2bfloat16(v);
    float r = v - __bfloat162float(hb);
    __nv_bfloat16 lb = __float2bfloat16(r);
    h = __bfloat16_as_ushort(hb);
    l = __bfloat16_as_ushort(lb);
}
__device__ __forceinline__ void ldsm_x4(uint32_t* r, uint32_t addr) {
    asm volatile("ldmatrix.sync.aligned.m8n8.x4.shared.b16 {%0,%1,%2,%3}, [%4];"
        : "=r"(r[0]), "=r"(r[1]), "=r"(r[2]), "=r"(r[3]) : "r"(addr));
}
__device__ __forceinline__ void ldsm_x4_t(uint32_t* r, uint32_t addr) {
    asm volatile("ldmatrix.sync.aligned.m8n8.x4.trans.shared.b16 {%0,%1,%2,%3}, [%4];"
        : "=r"(r[0]), "=r"(r[1]), "=r"(r[2]), "=r"(r[3]) : "r"(addr));
}
__device__ __forceinline__ void mma_bf16(float* c, const uint32_t* a,
                                         uint32_t b0, uint32_t b1) {
    asm volatile("mma.sync.aligned.m16n8k16.row.col.f32.bf16.bf16.f32 "
        "{%0,%1,%2,%3}, {%4,%5,%6,%7}, {%8,%9}, {%0,%1,%2,%3};"
        : "+f"(c[0]), "+f"(c[1]), "+f"(c[2]), "+f"(c[3])
        : "r"(a[0]), "r"(a[1]), "r"(a[2]), "r"(a[3]), "r"(b0), "r"(b1));
}
__device__ __forceinline__ void cp_async16(uint32_t dst, const void* src, int srcsz) {
    asm volatile("cp.async.cg.shared.global [%0], [%1], 16, %2;"
        :: "r"(dst), "l"(src), "r"(srcsz) : "memory");
}
#define CP_COMMIT() asm volatile("cp.async.commit_group;" ::: "memory")
#define CP_WAIT0()  asm volatile("cp.async.wait_group 0;" ::: "memory")
__device__ __forceinline__ int load_index(const void* p, long long i, int is64) {
    if (is64) return (int)((const long long*)p)[i];
    return ((const int*)p)[i];
}
__device__ __forceinline__ int probe_is64(const void* p) {
    const int* w32 = (const int*)p;
    int bad = 0;
    for (int j = threadIdx.x; j < 1024; j += blockDim.x)
        if (w32[2 * j + 1] != 0) bad = 1;
    return !__syncthreads_or(bad);
}

// ---------------- CSR: count ----------------
__global__ void count_kernel(const void* ei) {
    int is64 = probe_is64(ei);
    for (int e = blockIdx.x * blockDim.x + threadIdx.x; e < N_EDGES;
         e += gridDim.x * blockDim.x) {
        int d = load_index(ei, (long long)N_EDGES + e, is64);
        atomicAdd(&g_counts[d], 1);
    }
}

// ---------------- fused scan ----------------
__global__ void scanAB_kernel() {
    __shared__ int ws[8];
    __shared__ int amLast;
    int t = threadIdx.x, lane = t & 31, w = t >> 5;
    int i = blockIdx.x * 256 + t;
    int v = (i < N_NODES) ? g_counts[i] : 0;
    if (i < N_NODES) g_counts[i] = 0;
    int x = v;
#pragma unroll
    for (int o = 1; o < 32; o <<= 1) {
        int y = __shfl_up_sync(0xffffffffu, x, o);
        if (lane >= o) x += y;
    }
    if (lane == 31) ws[w] = x;
    __syncthreads();
    if (w == 0) {
        int y = (lane < 8) ? ws[lane] : 0;
#pragma unroll
        for (int o = 1; o < 32; o <<= 1) {
            int z = __shfl_up_sync(0xffffffffu, y, o);
            if (lane >= o) y += z;
        }
        if (lane < 8) ws[lane] = y;
    }
    __syncthreads();
    int pre = ((w > 0) ? ws[w - 1] : 0) + x - v;
    if (i <= N_NODES) g_offsets[i] = pre;
    if (i < N_NODES) g_cursor[i] = pre;
    if (t == 255) g_bsums[blockIdx.x] = ws[7];

    if (t == 0) {
        __threadfence();
        int k = atomicAdd(&g_tickA, 1);
        amLast = (k == SCAN_NBLK - 1);
        if (amLast) __threadfence();
    }
    __syncthreads();
    if (amLast) {
        int v2 = (t < SCAN_NBLK) ? g_bsums[t] : 0;
        int x2 = v2;
#pragma unroll
        for (int o = 1; o < 32; o <<= 1) {
            int y = __shfl_up_sync(0xffffffffu, x2, o);
            if (lane >= o) x2 += y;
        }
        __syncthreads();
        if (lane == 31) ws[w] = x2;
        __syncthreads();
        if (w == 0) {
            int y = (lane < 8) ? ws[lane] : 0;
#pragma unroll
            for (int o = 1; o < 32; o <<= 1) {
                int z = __shfl_up_sync(0xffffffffu, y, o);
                if (lane >= o) y += z;
            }
            if (lane < 8) ws[lane] = y;
        }
        __syncthreads();
        if (t < SCAN_NBLK) g_bpre[t] = ((w > 0) ? ws[w - 1] : 0) + x2 - v2;
        if (t == 0) g_tickA = 0;
    }
}

// ---------------- CSR: scatter ----------------
__global__ void scatter_kernel(const void* ei) {
    int is64 = probe_is64(ei);
    for (int e = blockIdx.x * blockDim.x + threadIdx.x; e < N_EDGES;
         e += gridDim.x * blockDim.x) {
        int s = load_index(ei, e, is64);
        int d = load_index(ei, (long long)N_EDGES + e, is64);
        int pos = g_bpre[d >> 8] + atomicAdd(&g_cursor[d], 1);
        g_srcidx[pos] = s;
    }
}

// ---------------- GIN aggregation (fp32 gather) -> bf16 hi/lo --------------
__global__ void agg_kernel(const float4* __restrict__ x4) {
    int node = blockIdx.x * 8 + (threadIdx.x >> 5);
    int lane = threadIdx.x & 31;
    if (node >= N_NODES) return;
    float4 acc = x4[node * 32 + lane];
    int e0 = g_offsets[node] + g_bpre[node >> 8];
    int e1 = g_offsets[node + 1] + g_bpre[(node + 1) >> 8];
    int e = e0;
    int n4 = e0 + ((e1 - e0) & ~3);
    for (; e < n4; e += 4) {
        int s0 = g_srcidx[e], s1 = g_srcidx[e + 1];
        int s2 = g_srcidx[e + 2], s3 = g_srcidx[e + 3];
        float4 v0 = x4[s0 * 32 + lane];
        float4 v1 = x4[s1 * 32 + lane];
        float4 v2 = x4[s2 * 32 + lane];
        float4 v3 = x4[s3 * 32 + lane];
        acc.x += v0.x + v1.x + v2.x + v3.x;
        acc.y += v0.y + v1.y + v2.y + v3.y;
        acc.z += v0.z + v1.z + v2.z + v3.z;
        acc.w += v0.w + v1.w + v2.w + v3.w;
    }
    for (; e < e1; e++) {
        int s = g_srcidx[e];
        float4 v = x4[s * 32 + lane];
        acc.x += v.x; acc.y += v.y; acc.z += v.z; acc.w += v.w;
    }
    float vv[4] = {acc.x, acc.y, acc.z, acc.w};
    unsigned short h[4], l[4];
#pragma unroll
    for (int i = 0; i < 4; i++) split_bf(vv[i], h[i], l[i]);
    uint2 hv = make_uint2((unsigned)h[0] | ((unsigned)h[1] << 16),
                          (unsigned)h[2] | ((unsigned)h[3] << 16));
    uint2 lv = make_uint2((unsigned)l[0] | ((unsigned)l[1] << 16),
                          (unsigned)l[2] | ((unsigned)l[3] << 16));
    ((uint2*)g_ahi)[node * 32 + lane] = hv;
    ((uint2*)g_alo)[node * 32 + lane] = lv;
}

// ---------------- fused dual GEMM (nn1 both layers) ------------------------
#define SA      0                 /* A/t1 tile: hi @ +0, lo @ +34816 */
#define ALO_OFF 34816
#define SWA_HI  69632
#define SWA_LO  104448
#define SWB_HI  139264
#define SWB_LO  174080
#define SBIAS1  208896
#define SBIAS2  209408
#define SBATCH  209920
#define GEMM_SMEM 210432

__device__ __forceinline__ void mainloop_128(uint32_t sbase, uint32_t wBase,
                                             uint32_t lOff, int m0, int n0,
                                             float c[2][8][4]) {
#pragma unroll
    for (int mh = 0; mh < 2; mh++)
#pragma unroll
        for (int j = 0; j < 8; j++)
#pragma unroll
            for (int q = 0; q < 4; q++) c[mh][j][q] = 0.f;

#pragma unroll 1
    for (int ks = 0; ks < 8; ks++) {
        uint32_t ah[2][4], al[2][4];
#pragma unroll
        for (int mh = 0; mh < 2; mh++) {
            uint32_t aa = sbase + SA + (uint32_t)(m0 + mh * 16) * 272 +
                          (uint32_t)ks * 32 + lOff;
            ldsm_x4(ah[mh], aa);
            ldsm_x4(al[mh], aa + ALO_OFF);
        }
#pragma unroll
        for (int nj = 0; nj < 4; nj++) {
            uint32_t bh[4], bl[4];
            uint32_t ba = sbase + wBase + (uint32_t)ks * 16 * 272 +
                          (uint32_t)(n0 + nj * 16) * 2 + lOff;
            ldsm_x4_t(bh, ba);
            ldsm_x4_t(bl, ba + ALO_OFF);
#pragma unroll
            for (int mh = 0; mh < 2; mh++) {
                mma_bf16(c[mh][2 * nj],     ah[mh], bh[0], bh[1]);
                mma_bf16(c[mh][2 * nj + 1], ah[mh], bh[2], bh[3]);
                mma_bf16(c[mh][2 * nj],     ah[mh], bl[0], bl[1]);
                mma_bf16(c[mh][2 * nj + 1], ah[mh], bl[2], bl[3]);
                mma_bf16(c[mh][2 * nj],     al[mh], bh[0], bh[1]);
                mma_bf16(c[mh][2 * nj + 1], al[mh], bh[2], bh[3]);
            }
        }
    }
}

__global__ __launch_bounds__(256, 1) void gemm_fused_kernel(
        const unsigned* __restrict__ Ahi, const unsigned* __restrict__ Alo,
        const float* __restrict__ W1a, const float* __restrict__ b1a,
        const float* __restrict__ W1b, const float* __restrict__ b1b,
        const void* __restrict__ batch, int M) {
    extern __shared__ char smem[];
    uint32_t sbase = smem_u32(smem);
    float* sBias1 = (float*)(smem + SBIAS1);
    float* sBias2 = (float*)(smem + SBIAS2);
    int* sB = (int*)(smem + SBATCH);
    int t = threadIdx.x;
    int lane = t & 31;
    int w = t >> 5;
    int wr = w >> 1, wc = w & 1;
    int m0 = wr * 32, n0 = wc * 64;
    int is64 = probe_is64(batch);

    {
        int tile0 = blockIdx.x;
        if (tile0 < NTILES) {
            int row0 = tile0 << 7;
            for (int idx = t; idx < 2048; idx += 256) {
                int r = idx >> 4, c4 = idx & 15;
                int gr = row0 + r;
                int ok = (gr < M) ? 16 : 0;
                int grc = ok ? gr : 0;
                cp_async16(sbase + SA + r * 272 + c4 * 16, Ahi + grc * 64 + c4 * 4, ok);
                cp_async16(sbase + SA + ALO_OFF + r * 272 + c4 * 16,
                           Alo + grc * 64 + c4 * 4, ok);
            }
        }
        CP_COMMIT();
    }

    for (int idx = t; idx < 128 * 128; idx += 256) {
        int k = idx >> 7, n = idx & 127;
        unsigned short h, l;
        split_bf(W1a[idx], h, l);
        *(unsigned short*)(smem + SWA_HI + (k * 136 + n) * 2) = h;
        *(unsigned short*)(smem + SWA_LO + (k * 136 + n) * 2) = l;
        split_bf(W1b[idx], h, l);
        *(unsigned short*)(smem + SWB_HI + (k * 136 + n) * 2) = h;
        *(unsigned short*)(smem + SWB_LO + (k * 136 + n) * 2) = l;
    }
    if (t < 128) { sBias1[t] = b1a[t]; sBias2[t] = b1b[t]; }

    int lrow = (lane & 7) + ((lane >> 3) & 1) * 8;
    int lcol = (lane >> 4) * 8;
    uint32_t lOff = (uint32_t)(lrow * 136 + lcol) * 2;
    int er = lane >> 2;
    int ec = 2 * (lane & 3);

    for (int tile = blockIdx.x; tile < NTILES; tile += gridDim.x) {
        int row0 = tile << 7;
        CP_WAIT0();
        __syncthreads();

        float c[2][8][4];
        mainloop_128(sbase, SWA_HI, lOff, m0, n0, c);
        __syncthreads();

#pragma unroll
        for (int mh = 0; mh < 2; mh++)
#pragma unroll
            for (int j = 0; j < 8; j++) {
                int n = n0 + j * 8 + ec;
                float b0 = sBias1[n], b1 = sBias1[n + 1];
                float* cc = c[mh][j];
                int r0 = m0 + mh * 16 + er;
                unsigned short h0, l0, h1, l1;
                split_bf(fmaxf(cc[0] + b0, 0.f), h0, l0);
                split_bf(fmaxf(cc[1] + b1, 0.f), h1, l1);
                *(unsigned*)(smem + SA + r0 * 272 + n * 2) =
                    (unsigned)h0 | ((unsigned)h1 << 16);
                *(unsigned*)(smem + SA + ALO_OFF + r0 * 272 + n * 2) =
                    (unsigned)l0 | ((unsigned)l1 << 16);
                split_bf(fmaxf(cc[2] + b0, 0.f), h0, l0);
                split_bf(fmaxf(cc[3] + b1, 0.f), h1, l1);
                *(unsigned*)(smem + SA + (r0 + 8) * 272 + n * 2) =
                    (unsigned)h0 | ((unsigned)h1 << 16);
                *(unsigned*)(smem + SA + ALO_OFF + (r0 + 8) * 272 + n * 2) =
                    (unsigned)l0 | ((unsigned)l1 << 16);
            }
        __syncthreads();

        mainloop_128(sbase, SWB_HI, lOff, m0, n0, c);
        __syncthreads();

        float* sV = (float*)(smem + SA);
#pragma unroll
        for (int mh = 0; mh < 2; mh++)
#pragma unroll
            for (int j = 0; j < 8; j++) {
                int n = n0 + j * 8 + ec;
                int rr = m0 + mh * 16 + er;
                float b0 = sBias2[n], b1 = sBias2[n + 1];
                float* cc = c[mh][j];
                *(float2*)&sV[rr * 132 + n] =
                    make_float2(fmaxf(cc[0] + b0, 0.f), fmaxf(cc[1] + b1, 0.f));
                *(float2*)&sV[(rr + 8) * 132 + n] =
                    make_float2(fmaxf(cc[2] + b0, 0.f), fmaxf(cc[3] + b1, 0.f));
            }
        if (t < 128) {
            int gr = row0 + t;
            sB[t] = (gr < M) ? load_index(batch, gr, is64) : -1;
        }
        __syncthreads();

        if (t < 128) {
            float s = 0.f, q = 0.f, run = 0.f;
            int cur = sB[0];
            for (int r = 0; r < 128; r++) {
                int b = sB[r];
                if (b != cur) {
                    if (cur >= 0) atomicAdd(&g_gsum[cur * NF + t], run);
                    run = 0.f;
                    cur = b;
                }
                if (b >= 0) {
                    float v = sV[r * 132 + t];
                    run += v;
                    s += v;
                    q += v * v;
                }
            }
            if (cur >= 0) atomicAdd(&g_gsum[cur * NF + t], run);
            atomicAdd(&g_stats[t], s);
            atomicAdd(&g_stats[128 + t], q);
        }
        __syncthreads();

        {
            int nt = tile + gridDim.x;
            if (nt < NTILES) {
                int row0n = nt << 7;
                for (int idx = t; idx < 2048; idx += 256) {
                    int r = idx >> 4, c4 = idx & 15;
                    int gr = row0n + r;
                    int ok = (gr < M) ? 16 : 0;
                    int grc = ok ? gr : 0;
                    cp_async16(sbase + SA + r * 272 + c4 * 16,
                               Ahi + grc * 64 + c4 * 4, ok);
                    cp_async16(sbase + SA + ALO_OFF + r * 272 + c4 * 16,
                               Alo + grc * 64 + c4 * 4, ok);
                }
            }
            CP_COMMIT();
        }
    }
}

// ---------------- tensor-core recurrence + output MLP ----------------------
// 16 blocks x 256 threads; block owns 16 graphs (M=16 rows).
// Per iteration: C[16,128] = cat[16,256] @ Wt[256,128] via bf16 hi/lo 3-term
// mma; bias + tanh/sigmoid; h re-split into the cat A-tile (k=128..255).
// Wt/cat layouts mirror the main GEMM (padded-stride ldsm tiles).
#define RW_HI   0                 /* Wt hi: 256 x 136 bf16 = 69632 B */
#define RW_LO   69632
#define RCAT_HI 139264            /* cat: 16 rows x 264 bf16 = 8448 B */
#define RCAT_LO 147712
#define RBIAS   156160            /* 128 floats */
#define RHFP    156672            /* h fp32: 16 x 132 floats = 8448 B */
#define RHID    165120            /* hid: 16 x 96 floats = 6144 B */
#define RSE     171264            /* 17 ints + flag */
#define RECUR_SMEM 171520
#define CAT_STRIDE 264            /* elements; 528 B rows (16B aligned) */

__global__ __launch_bounds__(256, 1) void recur_tc_kernel(
        const void* __restrict__ batch,
        const float* __restrict__ gamma, const float* __restrict__ beta,
        const float* __restrict__ Wl1, const float* __restrict__ bl1,
        const float* __restrict__ Wl2, const float* __restrict__ bl2,
        const float* __restrict__ Wm1, const float* __restrict__ bm1,
        const float* __restrict__ Wm2, const float* __restrict__ bm2,
        float* __restrict__ out) {
    extern __shared__ char smem[];
    uint32_t sbase = smem_u32(smem);
    float* sBias = (float*)(smem + RBIAS);
    float* hFP = (float*)(smem + RHFP);
    float* hid = (float*)(smem + RHID);
    int* se = (int*)(smem + RSE);           // [17] boundaries + [17] lastflag
    int t = threadIdx.x;
    int lane = t & 31;
    int w = t >> 5;                         // 0..7, n0 = w*16
    int n0 = w * 16;
    int g0 = blockIdx.x * 16;
    int is64 = probe_is64(batch);

    // graph boundaries
    if (t < 17) {
        int target = g0 + t;
        int lo = 0, hi = N_NODES;
        while (lo < hi) {
            int mid = (lo + hi) >> 1;
            int b = load_index(batch, mid, is64);
            if (b < target) lo = mid + 1; else hi = mid;
        }
        se[t] = lo;
    }

    // weights -> smem bf16 hi/lo (cols 0..63 = Wl2/tanh, 64..127 = Wl1/sigmoid)
    for (int idx = t; idx < 256 * 128; idx += 256) {
        int k = idx >> 7, n = idx & 127;
        float wv = (n < 64) ? Wl2[k * 64 + n] : Wl1[k * 64 + (n - 64)];
        unsigned short h, l;
        split_bf(wv, h, l);
        *(unsigned short*)(smem + RW_HI + (k * 136 + n) * 2) = h;
        *(unsigned short*)(smem + RW_LO + (k * 136 + n) * 2) = l;
    }
    if (t < 128) sBias[t] = (t < 64) ? bl2[t] : bl1[t - 64];

    // stats + own gsum (read, then ticketed zeroing)
    float ss = 0.f, sq = 0.f;
    if (t < 128) {
        ss = g_stats[t];
        sq = g_stats[128 + t];
    }
    __syncthreads();

    // BN-affine pooled means -> cat (xg half + h init), bf16 hi/lo
    if (t < 128) {
        float mu = ss / (float)N_NODES;
        float var = sq / (float)N_NODES - mu * mu;
        float rs = rsqrtf(var + BN_EPS);
        float gm = gamma[t], bt = beta[t];
        for (int r = 0; r < 16; r++) {
            float gsv = g_gsum[(g0 + r) * NF + t];
            g_gsum[(g0 + r) * NF + t] = 0.f;      // self-clean
            int cnt = se[r + 1] - se[r];
            float val = 0.f;
            if (cnt > 0) val = gm * (gsv / (float)cnt - mu) * rs + bt;
            unsigned short h, l;
            split_bf(val, h, l);
            *(unsigned short*)(smem + RCAT_HI + (r * CAT_STRIDE + t) * 2) = h;
            *(unsigned short*)(smem + RCAT_LO + (r * CAT_STRIDE + t) * 2) = l;
            *(unsigned short*)(smem + RCAT_HI + (r * CAT_STRIDE + 128 + t) * 2) = h;
            *(unsigned short*)(smem + RCAT_LO + (r * CAT_STRIDE + 128 + t) * 2) = l;
        }
    }
    if (t == 0) {
        __threadfence();
        int k = atomicAdd(&g_tickR, 1);
        se[17] = (k == 15);
    }
    __syncthreads();
    if (se[17]) {
        if (t < 256) g_stats[t] = 0.f;
        if (t == 0) g_tickR = 0;
    }
    __syncthreads();

    int lrow = (lane & 7) + ((lane >> 3) & 1) * 8;
    int lcol = (lane >> 4) * 8;
    int er = lane >> 2;
    int ec = 2 * (lane & 3);

    for (int it = 0; it < N_ITERS; it++) {
        float c[2][4];
#pragma unroll
        for (int j = 0; j < 2; j++)
#pragma unroll
            for (int q = 0; q < 4; q++) c[j][q] = 0.f;

#pragma unroll 2
        for (int ks = 0; ks < 16; ks++) {
            uint32_t ah[4], al[4], bh[4], bl[4];
            uint32_t aa = sbase + RCAT_HI +
                          (uint32_t)(lrow * CAT_STRIDE + ks * 16 + lcol) * 2;
            ldsm_x4(ah, aa);
            ldsm_x4(al, aa + (RCAT_LO - RCAT_HI));
            uint32_t ba = sbase + RW_HI +
                          (uint32_t)((ks * 16 + lrow) * 136 + n0 + lcol) * 2;
            ldsm_x4_t(bh, ba);
            ldsm_x4_t(bl, ba + (RW_LO - RW_HI));
            mma_bf16(c[0], ah, bh[0], bh[1]);
            mma_bf16(c[1], ah, bh[2], bh[3]);
            mma_bf16(c[0], ah, bl[0], bl[1]);
            mma_bf16(c[1], ah, bl[2], bl[3]);
            mma_bf16(c[0], al, bh[0], bh[1]);
            mma_bf16(c[1], al, bh[2], bh[3]);
        }
        __syncthreads();      // all warps done reading cat h-half

        // epilogue: bias + activation -> re-split into cat k=128..255
#pragma unroll
        for (int j = 0; j < 2; j++) {
            int nb = n0 + j * 8;
#pragma unroll
            for (int hcol = 0; hcol < 2; hcol++) {
                int n = nb + ec + hcol;
                float b = sBias[n];
                float o0 = c[j][hcol] + b;
                float o1 = c[j][2 + hcol] + b;
                float v0, v1;
                if (n < 64) {
                    v0 = tanhf(o0);
                    v1 = tanhf(o1);
                } else {
                    v0 = 1.0f / (1.0f + expf(-o0));
                    v1 = 1.0f / (1.0f + expf(-o1));
                }
                unsigned short h, l;
                split_bf(v0, h, l);
                *(unsigned short*)(smem + RCAT_HI + (er * CAT_STRIDE + 128 + n) * 2) = h;
                *(unsigned short*)(smem + RCAT_LO + (er * CAT_STRIDE + 128 + n) * 2) = l;
                split_bf(v1, h, l);
                *(unsigned short*)(smem + RCAT_HI + ((er + 8) * CAT_STRIDE + 128 + n) * 2) = h;
                *(unsigned short*)(smem + RCAT_LO + ((er + 8) * CAT_STRIDE + 128 + n) * 2) = l;
            }
        }
        __syncthreads();
    }

    // reconstruct h fp32 (hi+lo) for the output MLP
    for (int idx = t; idx < 16 * 128; idx += 256) {
        int r = idx >> 7, k = idx & 127;
        unsigned short h = *(unsigned short*)(smem + RCAT_HI + (r * CAT_STRIDE + 128 + k) * 2);
        unsigned short l = *(unsigned short*)(smem + RCAT_LO + (r * CAT_STRIDE + 128 + k) * 2);
        hFP[r * 132 + k] = __bfloat162float(__ushort_as_bfloat16(h)) +
                           __bfloat162float(__ushort_as_bfloat16(l));
    }
    __syncthreads();

    // hidden layer: thread = (graph r = t>>4, col group jj = t&15), 6 cols each
    {
        int r = t >> 4, jj = t & 15;
        const float* h = &hFP[r * 132];
        for (int j = jj * 6; j < jj * 6 + 6 && j < DIM; j++) {
            float a = bm1[j];
#pragma unroll 8
            for (int k = 0; k < NF; k++) a += h[k] * Wm1[k * DIM + j];
            hid[r * 96 + j] = fmaxf(a, 0.f);
        }
    }
    __syncthreads();

    // output layer
    {
        int r = t >> 4, col = t & 15;
        if (col < N_OUT) {
            float a = bm2[col];
            const float* hd = &hid[r * 96];
            for (int k = 0; k < DIM; k++) a += hd[k] * Wm2[k * N_OUT + col];
            out[(g0 + r) * N_OUT + col] = a;
        }
    }
}

// ---------------- host ----------------
extern "C" void kernel_launch(void* const* d_in, const int* in_sizes, int n_in,
                              void* d_out, int out_size) {
    const float* x     = (const float*)d_in[0];
    const void*  ei    = d_in[1];
    const void*  batch = d_in[2];
    const float* W1a = (const float*)d_in[3];
    const float* b1a = (const float*)d_in[4];
    const float* W1b = (const float*)d_in[5];
    const float* b1b = (const float*)d_in[6];
    const float* gamma = (const float*)d_in[7];
    const float* beta  = (const float*)d_in[8];
    const float* Wl1 = (const float*)d_in[9];
    const float* bl1 = (const float*)d_in[10];
    const float* Wl2 = (const float*)d_in[11];
    const float* bl2 = (const float*)d_in[12];
    const float* Wm1 = (const float*)d_in[13];
    const float* bm1 = (const float*)d_in[14];
    const float* Wm2 = (const float*)d_in[15];
    const float* bm2 = (const float*)d_in[16];
    float* out = (float*)d_out;

    void *p_ahi, *p_alo;
    cudaGetSymbolAddress(&p_ahi, g_ahi);
    cudaGetSymbolAddress(&p_alo, g_alo);

    cudaFuncSetAttribute(gemm_fused_kernel,
                         cudaFuncAttributeMaxDynamicSharedMemorySize, GEMM_SMEM);
    cudaFuncSetAttribute(recur_tc_kernel,
                         cudaFuncAttributeMaxDynamicSharedMemorySize, RECUR_SMEM);

    count_kernel<<<512, 256>>>(ei);
    scanAB_kernel<<<SCAN_NBLK, 256>>>();
    scatter_kernel<<<512, 256>>>(ei);
    agg_kernel<<<(N_NODES + 7) / 8, 256>>>((const float4*)x);
    gemm_fused_kernel<<<148, 256, GEMM_SMEM>>>(
        (const unsigned*)p_ahi, (const unsigned*)p_alo,
        W1a, b1a, W1b, b1b, batch, N_NODES);
    recur_tc_kernel<<<16, 256, RECUR_SMEM>>>(
        batch, gamma, beta, Wl1, bl1, Wl2, bl2, Wm1, bm1, Wm2, bm2, out);
}

// round 13
// speedup vs baseline: 1.0389x; 1.0389x over previous
#include <cuda_runtime.h>
#include <cuda_bf16.h>
#include <math.h>
#include <stdint.h>

#define N_NODES  50000
#define N_EDGES  600000
#define NF       128
#define N_GRAPHS 256
#define DIM      95
#define N_OUT    12
#define N_ITERS  10
#define BN_EPS   1e-5f
#define SCAN_NBLK 196
#define NTILES   391             // ceil(50000/128)

// ---------------- scratch (zero-initialized at load; self-cleaning) --------
__device__ unsigned g_ahi[N_NODES * 64];   // bf16x2 packed: (x+agg) hi
__device__ unsigned g_alo[N_NODES * 64];
__device__ int   g_counts[N_NODES];        // zeroed by scanAB after use
__device__ int   g_offsets[N_NODES + 1];   // block-local prefixes
__device__ int   g_cursor[N_NODES];
__device__ int   g_srcidx[N_EDGES];
__device__ int   g_bsums[SCAN_NBLK];
__device__ int   g_bpre[SCAN_NBLK];
__device__ float g_stats[2 * NF];          // zeroed by recur last block
__device__ float g_gsum[N_GRAPHS * NF];    // zeroed by its recur block
__device__ int   g_gcnt[N_GRAPHS];         // nodes per graph; zeroed by recur
__device__ float g_hout[N_GRAPHS * NF];    // recur output h (overwritten)
__device__ int   g_tickA;                  // self-resetting tickets
__device__ int   g_tickR;

// ---------------- helpers ----------------
__device__ __forceinline__ uint32_t smem_u32(const void* p) {
    uint32_t a;
    asm("{ .reg .u64 t; cvta.to.shared.u64 t, %1; cvt.u32.u64 %0, t; }" : "=r"(a) : "l"(p));
    return a;
}
__device__ __forceinline__ void split_bf(float v, unsigned short& h, unsigned short& l) {
    __nv_bfloat16 hb = __float2bfloat16(v);
    float r = v - __bfloat162float(hb);
    __nv_bfloat16 lb = __float2bfloat16(r);
    h = __bfloat16_as_ushort(hb);
    l = __bfloat16_as_ushort(lb);
}
__device__ __forceinline__ void ldsm_x4(uint32_t* r, uint32_t addr) {
    asm volatile("ldmatrix.sync.aligned.m8n8.x4.shared.b16 {%0,%1,%2,%3}, [%4];"
        : "=r"(r[0]), "=r"(r[1]), "=r"(r[2]), "=r"(r[3]) : "r"(addr));
}
__device__ __forceinline__ void ldsm_x4_t(uint32_t* r, uint32_t addr) {
    asm volatile("ldmatrix.sync.aligned.m8n8.x4.trans.shared.b16 {%0,%1,%2,%3}, [%4];"
        : "=r"(r[0]), "=r"(r[1]), "=r"(r[2]), "=r"(r[3]) : "r"(addr));
}
__device__ __forceinline__ void mma_bf16(float* c, const uint32_t* a,
                                         uint32_t b0, uint32_t b1) {
    asm volatile("mma.sync.aligned.m16n8k16.row.col.f32.bf16.bf16.f32 "
        "{%0,%1,%2,%3}, {%4,%5,%6,%7}, {%8,%9}, {%0,%1,%2,%3};"
        : "+f"(c[0]), "+f"(c[1]), "+f"(c[2]), "+f"(c[3])
        : "r"(a[0]), "r"(a[1]), "r"(a[2]), "r"(a[3]), "r"(b0), "r"(b1));
}
__device__ __forceinline__ void cp_async16(uint32_t dst, const void* src, int srcsz) {
    asm volatile("cp.async.cg.shared.global [%0], [%1], 16, %2;"
        :: "r"(dst), "l"(src), "r"(srcsz) : "memory");
}
#define CP_COMMIT() asm volatile("cp.async.commit_group;" ::: "memory")
#define CP_WAIT0()  asm volatile("cp.async.wait_group 0;" ::: "memory")
__device__ __forceinline__ int load_index(const void* p, long long i, int is64) {
    if (is64) return (int)((const long long*)p)[i];
    return ((const int*)p)[i];
}
__device__ __forceinline__ int probe_is64(const void* p) {
    const int* w32 = (const int*)p;
    int bad = 0;
    for (int j = threadIdx.x; j < 1024; j += blockDim.x)
        if (w32[2 * j + 1] != 0) bad = 1;
    return !__syncthreads_or(bad);
}

// ---------------- CSR: count (+ batch histogram for graph sizes) -----------
__global__ void count_kernel(const void* ei, const void* batch) {
    int is64e = probe_is64(ei);
    int is64b = probe_is64(batch);
    int gtid = blockIdx.x * blockDim.x + threadIdx.x;
    int gstride = gridDim.x * blockDim.x;
    for (int e = gtid; e < N_EDGES; e += gstride) {
        int d = load_index(ei, (long long)N_EDGES + e, is64e);
        atomicAdd(&g_counts[d], 1);
    }
    for (int i = gtid; i < N_NODES; i += gstride) {
        int b = load_index(batch, i, is64b);
        atomicAdd(&g_gcnt[b], 1);
    }
}

// ---------------- fused scan ----------------
__global__ void scanAB_kernel() {
    __shared__ int ws[8];
    __shared__ int amLast;
    int t = threadIdx.x, lane = t & 31, w = t >> 5;
    int i = blockIdx.x * 256 + t;
    int v = (i < N_NODES) ? g_counts[i] : 0;
    if (i < N_NODES) g_counts[i] = 0;
    int x = v;
#pragma unroll
    for (int o = 1; o < 32; o <<= 1) {
        int y = __shfl_up_sync(0xffffffffu, x, o);
        if (lane >= o) x += y;
    }
    if (lane == 31) ws[w] = x;
    __syncthreads();
    if (w == 0) {
        int y = (lane < 8) ? ws[lane] : 0;
#pragma unroll
        for (int o = 1; o < 32; o <<= 1) {
            int z = __shfl_up_sync(0xffffffffu, y, o);
            if (lane >= o) y += z;
        }
        if (lane < 8) ws[lane] = y;
    }
    __syncthreads();
    int pre = ((w > 0) ? ws[w - 1] : 0) + x - v;
    if (i <= N_NODES) g_offsets[i] = pre;
    if (i < N_NODES) g_cursor[i] = pre;
    if (t == 255) g_bsums[blockIdx.x] = ws[7];

    if (t == 0) {
        __threadfence();
        int k = atomicAdd(&g_tickA, 1);
        amLast = (k == SCAN_NBLK - 1);
        if (amLast) __threadfence();
    }
    __syncthreads();
    if (amLast) {
        int v2 = (t < SCAN_NBLK) ? g_bsums[t] : 0;
        int x2 = v2;
#pragma unroll
        for (int o = 1; o < 32; o <<= 1) {
            int y = __shfl_up_sync(0xffffffffu, x2, o);
            if (lane >= o) x2 += y;
        }
        __syncthreads();
        if (lane == 31) ws[w] = x2;
        __syncthreads();
        if (w == 0) {
            int y = (lane < 8) ? ws[lane] : 0;
#pragma unroll
            for (int o = 1; o < 32; o <<= 1) {
                int z = __shfl_up_sync(0xffffffffu, y, o);
                if (lane >= o) y += z;
            }
            if (lane < 8) ws[lane] = y;
        }
        __syncthreads();
        if (t < SCAN_NBLK) g_bpre[t] = ((w > 0) ? ws[w - 1] : 0) + x2 - v2;
        if (t == 0) g_tickA = 0;
    }
}

// ---------------- CSR: scatter ----------------
__global__ void scatter_kernel(const void* ei) {
    int is64 = probe_is64(ei);
    for (int e = blockIdx.x * blockDim.x + threadIdx.x; e < N_EDGES;
         e += gridDim.x * blockDim.x) {
        int s = load_index(ei, e, is64);
        int d = load_index(ei, (long long)N_EDGES + e, is64);
        int pos = g_bpre[d >> 8] + atomicAdd(&g_cursor[d], 1);
        g_srcidx[pos] = s;
    }
}

// ---------------- GIN aggregation (fp32 gather) -> bf16 hi/lo --------------
__global__ void agg_kernel(const float4* __restrict__ x4) {
    int node = blockIdx.x * 8 + (threadIdx.x >> 5);
    int lane = threadIdx.x & 31;
    if (node >= N_NODES) return;
    float4 acc = x4[node * 32 + lane];
    int e0 = g_offsets[node] + g_bpre[node >> 8];
    int e1 = g_offsets[node + 1] + g_bpre[(node + 1) >> 8];
    int e = e0;
    int n4 = e0 + ((e1 - e0) & ~3);
    for (; e < n4; e += 4) {
        int s0 = g_srcidx[e], s1 = g_srcidx[e + 1];
        int s2 = g_srcidx[e + 2], s3 = g_srcidx[e + 3];
        float4 v0 = x4[s0 * 32 + lane];
        float4 v1 = x4[s1 * 32 + lane];
        float4 v2 = x4[s2 * 32 + lane];
        float4 v3 = x4[s3 * 32 + lane];
        acc.x += v0.x + v1.x + v2.x + v3.x;
        acc.y += v0.y + v1.y + v2.y + v3.y;
        acc.z += v0.z + v1.z + v2.z + v3.z;
        acc.w += v0.w + v1.w + v2.w + v3.w;
    }
    for (; e < e1; e++) {
        int s = g_srcidx[e];
        float4 v = x4[s * 32 + lane];
        acc.x += v.x; acc.y += v.y; acc.z += v.z; acc.w += v.w;
    }
    float vv[4] = {acc.x, acc.y, acc.z, acc.w};
    unsigned short h[4], l[4];
#pragma unroll
    for (int i = 0; i < 4; i++) split_bf(vv[i], h[i], l[i]);
    uint2 hv = make_uint2((unsigned)h[0] | ((unsigned)h[1] << 16),
                          (unsigned)h[2] | ((unsigned)h[3] << 16));
    uint2 lv = make_uint2((unsigned)l[0] | ((unsigned)l[1] << 16),
                          (unsigned)l[2] | ((unsigned)l[3] << 16));
    ((uint2*)g_ahi)[node * 32 + lane] = hv;
    ((uint2*)g_alo)[node * 32 + lane] = lv;
}

// ---------------- fused dual GEMM (nn1 both layers) ------------------------
#define SA      0                 /* A/t1 tile: hi @ +0, lo @ +34816 */
#define ALO_OFF 34816
#define SWA_HI  69632
#define SWA_LO  104448
#define SWB_HI  139264
#define SWB_LO  174080
#define SBIAS1  208896
#define SBIAS2  209408
#define SBATCH  209920
#define GEMM_SMEM 210432

__device__ __forceinline__ void mainloop_128(uint32_t sbase, uint32_t wBase,
                                             uint32_t lOff, int m0, int n0,
                                             float c[2][8][4]) {
#pragma unroll
    for (int mh = 0; mh < 2; mh++)
#pragma unroll
        for (int j = 0; j < 8; j++)
#pragma unroll
            for (int q = 0; q < 4; q++) c[mh][j][q] = 0.f;

#pragma unroll 1
    for (int ks = 0; ks < 8; ks++) {
        uint32_t ah[2][4], al[2][4];
#pragma unroll
        for (int mh = 0; mh < 2; mh++) {
            uint32_t aa = sbase + SA + (uint32_t)(m0 + mh * 16) * 272 +
                          (uint32_t)ks * 32 + lOff;
            ldsm_x4(ah[mh], aa);
            ldsm_x4(al[mh], aa + ALO_OFF);
        }
#pragma unroll
        for (int nj = 0; nj < 4; nj++) {
            uint32_t bh[4], bl[4];
            uint32_t ba = sbase + wBase + (uint32_t)ks * 16 * 272 +
                          (uint32_t)(n0 + nj * 16) * 2 + lOff;
            ldsm_x4_t(bh, ba);
            ldsm_x4_t(bl, ba + ALO_OFF);
#pragma unroll
            for (int mh = 0; mh < 2; mh++) {
                mma_bf16(c[mh][2 * nj],     ah[mh], bh[0], bh[1]);
                mma_bf16(c[mh][2 * nj + 1], ah[mh], bh[2], bh[3]);
                mma_bf16(c[mh][2 * nj],     ah[mh], bl[0], bl[1]);
                mma_bf16(c[mh][2 * nj + 1], ah[mh], bl[2], bl[3]);
                mma_bf16(c[mh][2 * nj],     al[mh], bh[0], bh[1]);
                mma_bf16(c[mh][2 * nj + 1], al[mh], bh[2], bh[3]);
            }
        }
    }
}

__global__ __launch_bounds__(256, 1) void gemm_fused_kernel(
        const unsigned* __restrict__ Ahi, const unsigned* __restrict__ Alo,
        const float* __restrict__ W1a, const float* __restrict__ b1a,
        const float* __restrict__ W1b, const float* __restrict__ b1b,
        const void* __restrict__ batch, int M) {
    extern __shared__ char smem[];
    uint32_t sbase = smem_u32(smem);
    float* sBias1 = (float*)(smem + SBIAS1);
    float* sBias2 = (float*)(smem + SBIAS2);
    int* sB = (int*)(smem + SBATCH);
    int t = threadIdx.x;
    int lane = t & 31;
    int w = t >> 5;
    int wr = w >> 1, wc = w & 1;
    int m0 = wr * 32, n0 = wc * 64;
    int is64 = probe_is64(batch);

    {
        int tile0 = blockIdx.x;
        if (tile0 < NTILES) {
            int row0 = tile0 << 7;
            for (int idx = t; idx < 2048; idx += 256) {
                int r = idx >> 4, c4 = idx & 15;
                int gr = row0 + r;
                int ok = (gr < M) ? 16 : 0;
                int grc = ok ? gr : 0;
                cp_async16(sbase + SA + r * 272 + c4 * 16, Ahi + grc * 64 + c4 * 4, ok);
                cp_async16(sbase + SA + ALO_OFF + r * 272 + c4 * 16,
                           Alo + grc * 64 + c4 * 4, ok);
            }
        }
        CP_COMMIT();
    }

    for (int idx = t; idx < 128 * 128; idx += 256) {
        int k = idx >> 7, n = idx & 127;
        unsigned short h, l;
        split_bf(W1a[idx], h, l);
        *(unsigned short*)(smem + SWA_HI + (k * 136 + n) * 2) = h;
        *(unsigned short*)(smem + SWA_LO + (k * 136 + n) * 2) = l;
        split_bf(W1b[idx], h, l);
        *(unsigned short*)(smem + SWB_HI + (k * 136 + n) * 2) = h;
        *(unsigned short*)(smem + SWB_LO + (k * 136 + n) * 2) = l;
    }
    if (t < 128) { sBias1[t] = b1a[t]; sBias2[t] = b1b[t]; }

    int lrow = (lane & 7) + ((lane >> 3) & 1) * 8;
    int lcol = (lane >> 4) * 8;
    uint32_t lOff = (uint32_t)(lrow * 136 + lcol) * 2;
    int er = lane >> 2;
    int ec = 2 * (lane & 3);

    for (int tile = blockIdx.x; tile < NTILES; tile += gridDim.x) {
        int row0 = tile << 7;
        CP_WAIT0();
        __syncthreads();

        float c[2][8][4];
        mainloop_128(sbase, SWA_HI, lOff, m0, n0, c);
        __syncthreads();

#pragma unroll
        for (int mh = 0; mh < 2; mh++)
#pragma unroll
            for (int j = 0; j < 8; j++) {
                int n = n0 + j * 8 + ec;
                float b0 = sBias1[n], b1 = sBias1[n + 1];
                float* cc = c[mh][j];
                int r0 = m0 + mh * 16 + er;
                unsigned short h0, l0, h1, l1;
                split_bf(fmaxf(cc[0] + b0, 0.f), h0, l0);
                split_bf(fmaxf(cc[1] + b1, 0.f), h1, l1);
                *(unsigned*)(smem + SA + r0 * 272 + n * 2) =
                    (unsigned)h0 | ((unsigned)h1 << 16);
                *(unsigned*)(smem + SA + ALO_OFF + r0 * 272 + n * 2) =
                    (unsigned)l0 | ((unsigned)l1 << 16);
                split_bf(fmaxf(cc[2] + b0, 0.f), h0, l0);
                split_bf(fmaxf(cc[3] + b1, 0.f), h1, l1);
                *(unsigned*)(smem + SA + (r0 + 8) * 272 + n * 2) =
                    (unsigned)h0 | ((unsigned)h1 << 16);
                *(unsigned*)(smem + SA + ALO_OFF + (r0 + 8) * 272 + n * 2) =
                    (unsigned)l0 | ((unsigned)l1 << 16);
            }
        __syncthreads();

        mainloop_128(sbase, SWB_HI, lOff, m0, n0, c);
        __syncthreads();

        float* sV = (float*)(smem + SA);
#pragma unroll
        for (int mh = 0; mh < 2; mh++)
#pragma unroll
            for (int j = 0; j < 8; j++) {
                int n = n0 + j * 8 + ec;
                int rr = m0 + mh * 16 + er;
                float b0 = sBias2[n], b1 = sBias2[n + 1];
                float* cc = c[mh][j];
                *(float2*)&sV[rr * 132 + n] =
                    make_float2(fmaxf(cc[0] + b0, 0.f), fmaxf(cc[1] + b1, 0.f));
                *(float2*)&sV[(rr + 8) * 132 + n] =
                    make_float2(fmaxf(cc[2] + b0, 0.f), fmaxf(cc[3] + b1, 0.f));
            }
        if (t < 128) {
            int gr = row0 + t;
            sB[t] = (gr < M) ? load_index(batch, gr, is64) : -1;
        }
        __syncthreads();

        if (t < 128) {
            float s = 0.f, q = 0.f, run = 0.f;
            int cur = sB[0];
            for (int r = 0; r < 128; r++) {
                int b = sB[r];
                if (b != cur) {
                    if (cur >= 0) atomicAdd(&g_gsum[cur * NF + t], run);
                    run = 0.f;
                    cur = b;
                }
                if (b >= 0) {
                    float v = sV[r * 132 + t];
                    run += v;
                    s += v;
                    q += v * v;
                }
            }
            if (cur >= 0) atomicAdd(&g_gsum[cur * NF + t], run);
            atomicAdd(&g_stats[t], s);
            atomicAdd(&g_stats[128 + t], q);
        }
        __syncthreads();

        {
            int nt = tile + gridDim.x;
            if (nt < NTILES) {
                int row0n = nt << 7;
                for (int idx = t; idx < 2048; idx += 256) {
                    int r = idx >> 4, c4 = idx & 15;
                    int gr = row0n + r;
                    int ok = (gr < M) ? 16 : 0;
                    int grc = ok ? gr : 0;
                    cp_async16(sbase + SA + r * 272 + c4 * 16,
                               Ahi + grc * 64 + c4 * 4, ok);
                    cp_async16(sbase + SA + ALO_OFF + r * 272 + c4 * 16,
                               Alo + grc * 64 + c4 * 4, ok);
                }
            }
            CP_COMMIT();
        }
    }
}

// ---------------- tensor-core recurrence (recurrence ONLY) -----------------
// 16 blocks x 256 threads; block owns 16 graphs (M=16 rows).
// Per iteration: C[16,128] = cat[16,256] @ Wt[256,128] via bf16 hi/lo 3-term
// mma; bias + tanh/sigmoid; h re-split into the cat A-tile (k=128..255).
// Writes final h (fp32) to g_hout; MLP runs in a separate coalesced kernel.
#define RW_HI   0                 /* Wt hi: 256 x 136 bf16 = 69632 B */
#define RW_LO   69632
#define RCAT_HI 139264            /* cat: 16 rows x 264 bf16 = 8448 B */
#define RCAT_LO 147712
#define RBIAS   156160            /* 128 floats */
#define RFLAG   156672
#define RECUR_SMEM 156800
#define CAT_STRIDE 264            /* elements; 528 B rows (16B aligned) */

__global__ __launch_bounds__(256, 1) void recur_tc_kernel(
        const float* __restrict__ gamma, const float* __restrict__ beta,
        const float* __restrict__ Wl1, const float* __restrict__ bl1,
        const float* __restrict__ Wl2, const float* __restrict__ bl2) {
    extern __shared__ char smem[];
    uint32_t sbase = smem_u32(smem);
    float* sBias = (float*)(smem + RBIAS);
    int* flag = (int*)(smem + RFLAG);
    int t = threadIdx.x;
    int lane = t & 31;
    int w = t >> 5;                         // 0..7, n0 = w*16
    int n0 = w * 16;
    int g0 = blockIdx.x * 16;

    // weights -> smem bf16 hi/lo (cols 0..63 = Wl2/tanh, 64..127 = Wl1/sigmoid)
    for (int idx = t; idx < 256 * 128; idx += 256) {
        int k = idx >> 7, n = idx & 127;
        float wv = (n < 64) ? Wl2[k * 64 + n] : Wl1[k * 64 + (n - 64)];
        unsigned short h, l;
        split_bf(wv, h, l);
        *(unsigned short*)(smem + RW_HI + (k * 136 + n) * 2) = h;
        *(unsigned short*)(smem + RW_LO + (k * 136 + n) * 2) = l;
    }
    if (t < 128) sBias[t] = (t < 64) ? bl2[t] : bl1[t - 64];

    // BN-affine pooled means -> cat (xg half + h init), bf16 hi/lo
    if (t < 128) {
        float ss = g_stats[t];
        float sq = g_stats[128 + t];
        float mu = ss / (float)N_NODES;
        float var = sq / (float)N_NODES - mu * mu;
        float rs = rsqrtf(var + BN_EPS);
        float gm = gamma[t], bt = beta[t];
        for (int r = 0; r < 16; r++) {
            float gsv = g_gsum[(g0 + r) * NF + t];
            g_gsum[(g0 + r) * NF + t] = 0.f;      // self-clean
            int cnt = g_gcnt[g0 + r];
            float val = 0.f;
            if (cnt > 0) val = gm * (gsv / (float)cnt - mu) * rs + bt;
            unsigned short h, l;
            split_bf(val, h, l);
            *(unsigned short*)(smem + RCAT_HI + (r * CAT_STRIDE + t) * 2) = h;
            *(unsigned short*)(smem + RCAT_LO + (r * CAT_STRIDE + t) * 2) = l;
            *(unsigned short*)(smem + RCAT_HI + (r * CAT_STRIDE + 128 + t) * 2) = h;
            *(unsigned short*)(smem + RCAT_LO + (r * CAT_STRIDE + 128 + t) * 2) = l;
        }
    }
    __syncthreads();
    if (t < 16) g_gcnt[g0 + t] = 0;               // self-clean (post-read)
    if (t == 0) {
        __threadfence();
        int k = atomicAdd(&g_tickR, 1);
        *flag = (k == 15);
    }
    __syncthreads();
    if (*flag) {
        if (t < 256) g_stats[t] = 0.f;
        if (t == 0) g_tickR = 0;
    }

    int lrow = (lane & 7) + ((lane >> 3) & 1) * 8;
    int lcol = (lane >> 4) * 8;
    int er = lane >> 2;
    int ec = 2 * (lane & 3);

    for (int it = 0; it < N_ITERS; it++) {
        float c[2][4];
#pragma unroll
        for (int j = 0; j < 2; j++)
#pragma unroll
            for (int q = 0; q < 4; q++) c[j][q] = 0.f;

#pragma unroll 2
        for (int ks = 0; ks < 16; ks++) {
            uint32_t ah[4], al[4], bh[4], bl[4];
            uint32_t aa = sbase + RCAT_HI +
                          (uint32_t)(lrow * CAT_STRIDE + ks * 16 + lcol) * 2;
            ldsm_x4(ah, aa);
            ldsm_x4(al, aa + (RCAT_LO - RCAT_HI));
            uint32_t ba = sbase + RW_HI +
                          (uint32_t)((ks * 16 + lrow) * 136 + n0 + lcol) * 2;
            ldsm_x4_t(bh, ba);
            ldsm_x4_t(bl, ba + (RW_LO - RW_HI));
            mma_bf16(c[0], ah, bh[0], bh[1]);
            mma_bf16(c[1], ah, bh[2], bh[3]);
            mma_bf16(c[0], ah, bl[0], bl[1]);
            mma_bf16(c[1], ah, bl[2], bl[3]);
            mma_bf16(c[0], al, bh[0], bh[1]);
            mma_bf16(c[1], al, bh[2], bh[3]);
        }
        __syncthreads();      // all warps done reading cat h-half

        // epilogue: bias + activation -> re-split into cat k=128..255
#pragma unroll
        for (int j = 0; j < 2; j++) {
            int nb = n0 + j * 8;
#pragma unroll
            for (int hcol = 0; hcol < 2; hcol++) {
                int n = nb + ec + hcol;
                float b = sBias[n];
                float o0 = c[j][hcol] + b;
                float o1 = c[j][2 + hcol] + b;
                float v0, v1;
                if (n < 64) {
                    v0 = tanhf(o0);
                    v1 = tanhf(o1);
                } else {
                    v0 = 1.0f / (1.0f + expf(-o0));
                    v1 = 1.0f / (1.0f + expf(-o1));
                }
                unsigned short h, l;
                split_bf(v0, h, l);
                *(unsigned short*)(smem + RCAT_HI + (er * CAT_STRIDE + 128 + n) * 2) = h;
                *(unsigned short*)(smem + RCAT_LO + (er * CAT_STRIDE + 128 + n) * 2) = l;
                split_bf(v1, h, l);
                *(unsigned short*)(smem + RCAT_HI + ((er + 8) * CAT_STRIDE + 128 + n) * 2) = h;
                *(unsigned short*)(smem + RCAT_LO + ((er + 8) * CAT_STRIDE + 128 + n) * 2) = l;
            }
        }
        __syncthreads();
    }

    // reconstruct h fp32 (hi+lo) -> global for the MLP kernel
    for (int idx = t; idx < 16 * 128; idx += 256) {
        int r = idx >> 7, k = idx & 127;
        unsigned short h = *(unsigned short*)(smem + RCAT_HI + (r * CAT_STRIDE + 128 + k) * 2);
        unsigned short l = *(unsigned short*)(smem + RCAT_LO + (r * CAT_STRIDE + 128 + k) * 2);
        g_hout[(g0 + r) * NF + k] =
            __bfloat162float(__ushort_as_bfloat16(h)) +
            __bfloat162float(__ushort_as_bfloat16(l));
    }
}

// ---------------- output MLP (coalesced, one graph per block) --------------
__global__ void mlp_kernel(const float* __restrict__ Wm1, const float* __restrict__ bm1,
                           const float* __restrict__ Wm2, const float* __restrict__ bm2,
                           float* __restrict__ out) {
    int g = blockIdx.x;
    int t = threadIdx.x;   // 128
    __shared__ float hrow[NF];
    __shared__ float hid[DIM];
    hrow[t] = g_hout[g * NF + t];
    __syncthreads();
    if (t < DIM) {
        float a = bm1[t];
#pragma unroll 8
        for (int k = 0; k < NF; k++) a += hrow[k] * Wm1[k * DIM + t];
        hid[t] = fmaxf(a, 0.f);
    }
    __syncthreads();
    if (t < N_OUT) {
        float a = bm2[t];
        for (int k = 0; k < DIM; k++) a += hid[k] * Wm2[k * N_OUT + t];
        out[g * N_OUT + t] = a;
    }
}

// ---------------- host ----------------
extern "C" void kernel_launch(void* const* d_in, const int* in_sizes, int n_in,
                              void* d_out, int out_size) {
    const float* x     = (const float*)d_in[0];
    const void*  ei    = d_in[1];
    const void*  batch = d_in[2];
    const float* W1a = (const float*)d_in[3];
    const float* b1a = (const float*)d_in[4];
    const float* W1b = (const float*)d_in[5];
    const float* b1b = (const float*)d_in[6];
    const float* gamma = (const float*)d_in[7];
    const float* beta  = (const float*)d_in[8];
    const float* Wl1 = (const float*)d_in[9];
    const float* bl1 = (const float*)d_in[10];
    const float* Wl2 = (const float*)d_in[11];
    const float* bl2 = (const float*)d_in[12];
    const float* Wm1 = (const float*)d_in[13];
    const float* bm1 = (const float*)d_in[14];
    const float* Wm2 = (const float*)d_in[15];
    const float* bm2 = (const float*)d_in[16];
    float* out = (float*)d_out;

    void *p_ahi, *p_alo;
    cudaGetSymbolAddress(&p_ahi, g_ahi);
    cudaGetSymbolAddress(&p_alo, g_alo);

    cudaFuncSetAttribute(gemm_fused_kernel,
                         cudaFuncAttributeMaxDynamicSharedMemorySize, GEMM_SMEM);
    cudaFuncSetAttribute(recur_tc_kernel,
                         cudaFuncAttributeMaxDynamicSharedMemorySize, RECUR_SMEM);

    count_kernel<<<512, 256>>>(ei, batch);
    scanAB_kernel<<<SCAN_NBLK, 256>>>();
    scatter_kernel<<<512, 256>>>(ei);
    agg_kernel<<<(N_NODES + 7) / 8, 256>>>((const float4*)x);
    gemm_fused_kernel<<<148, 256, GEMM_SMEM>>>(
        (const unsigned*)p_ahi, (const unsigned*)p_alo,
        W1a, b1a, W1b, b1b, batch, N_NODES);
    recur_tc_kernel<<<16, 256, RECUR_SMEM>>>(gamma, beta, Wl1, bl1, Wl2, bl2);
    mlp_kernel<<<N_GRAPHS, 128>>>(Wm1, bm1, Wm2, bm2, out);
}

// round 14
// speedup vs baseline: 1.2386x; 1.1922x over previous
#include <cuda_runtime.h>
#include <cuda_bf16.h>
#include <math.h>
#include <stdint.h>

#define N_NODES  50000
#define N_EDGES  600000
#define NF       128
#define N_GRAPHS 256
#define DIM      95
#define N_OUT    12
#define N_ITERS  10
#define BN_EPS   1e-5f
#define SCAN_NBLK 196
#define NTILES   391             // ceil(50000/128)

// ---------------- scratch (zero-initialized at load; self-cleaning) --------
__device__ unsigned g_ahi[N_NODES * 64];   // bf16x2 packed: (x+agg) hi
__device__ unsigned g_alo[N_NODES * 64];
__device__ int   g_counts[N_NODES];        // zeroed by scanAB after use
__device__ int   g_offsets[N_NODES + 1];   // block-local prefixes
__device__ int   g_cursor[N_NODES];
__device__ int   g_srcidx[N_EDGES];
__device__ int   g_bsums[SCAN_NBLK];
__device__ int   g_bpre[SCAN_NBLK];
__device__ float g_stats[2 * NF];          // zeroed by recur last block
__device__ float g_gsum[N_GRAPHS * NF];    // zeroed by its recur block
__device__ int   g_tickA;                  // self-resetting tickets
__device__ int   g_tickR;

// ---------------- helpers ----------------
__device__ __forceinline__ uint32_t smem_u32(const void* p) {
    uint32_t a;
    asm("{ .reg .u64 t; cvta.to.shared.u64 t, %1; cvt.u32.u64 %0, t; }" : "=r"(a) : "l"(p));
    return a;
}
__device__ __forceinline__ void split_bf(float v, unsigned short& h, unsigned short& l) {
    __nv_bfloat16 hb = __float2bfloat16(v);
    float r = v - __bfloat162float(hb);
    __nv_bfloat16 lb = __float2bfloat16(r);
    h = __bfloat16_as_ushort(hb);
    l = __bfloat16_as_ushort(lb);
}
__device__ __forceinline__ void ldsm_x4(uint32_t* r, uint32_t addr) {
    asm volatile("ldmatrix.sync.aligned.m8n8.x4.shared.b16 {%0,%1,%2,%3}, [%4];"
        : "=r"(r[0]), "=r"(r[1]), "=r"(r[2]), "=r"(r[3]) : "r"(addr));
}
__device__ __forceinline__ void ldsm_x4_t(uint32_t* r, uint32_t addr) {
    asm volatile("ldmatrix.sync.aligned.m8n8.x4.trans.shared.b16 {%0,%1,%2,%3}, [%4];"
        : "=r"(r[0]), "=r"(r[1]), "=r"(r[2]), "=r"(r[3]) : "r"(addr));
}
__device__ __forceinline__ void mma_bf16(float* c, const uint32_t* a,
                                         uint32_t b0, uint32_t b1) {
    asm volatile("mma.sync.aligned.m16n8k16.row.col.f32.bf16.bf16.f32 "
        "{%0,%1,%2,%3}, {%4,%5,%6,%7}, {%8,%9}, {%0,%1,%2,%3};"
        : "+f"(c[0]), "+f"(c[1]), "+f"(c[2]), "+f"(c[3])
        : "r"(a[0]), "r"(a[1]), "r"(a[2]), "r"(a[3]), "r"(b0), "r"(b1));
}
__device__ __forceinline__ void cp_async16(uint32_t dst, const void* src, int srcsz) {
    asm volatile("cp.async.cg.shared.global [%0], [%1], 16, %2;"
        :: "r"(dst), "l"(src), "r"(srcsz) : "memory");
}
#define CP_COMMIT() asm volatile("cp.async.commit_group;" ::: "memory")
#define CP_WAIT0()  asm volatile("cp.async.wait_group 0;" ::: "memory")
__device__ __forceinline__ int load_index(const void* p, long long i, int is64) {
    if (is64) return (int)((const long long*)p)[i];
    return ((const int*)p)[i];
}
__device__ __forceinline__ int probe_is64(const void* p) {
    const int* w32 = (const int*)p;
    int bad = 0;
    for (int j = threadIdx.x; j < 1024; j += blockDim.x)
        if (w32[2 * j + 1] != 0) bad = 1;
    return !__syncthreads_or(bad);
}
__device__ __forceinline__ unsigned long long pack_f32x2(float lo, float hi) {
    unsigned long long u;
    asm("mov.b64 %0, {%1, %2};" : "=l"(u) : "f"(lo), "f"(hi));
    return u;
}
__device__ __forceinline__ void unpack_f32x2(unsigned long long u, float& lo, float& hi) {
    asm("mov.b64 {%0, %1}, %2;" : "=f"(lo), "=f"(hi) : "l"(u));
}

// ---------------- CSR: count ----------------
__global__ void count_kernel(const void* ei) {
    int is64 = probe_is64(ei);
    for (int e = blockIdx.x * blockDim.x + threadIdx.x; e < N_EDGES;
         e += gridDim.x * blockDim.x) {
        int d = load_index(ei, (long long)N_EDGES + e, is64);
        atomicAdd(&g_counts[d], 1);
    }
}

// ---------------- fused scan ----------------
__global__ void scanAB_kernel() {
    __shared__ int ws[8];
    __shared__ int amLast;
    int t = threadIdx.x, lane = t & 31, w = t >> 5;
    int i = blockIdx.x * 256 + t;
    int v = (i < N_NODES) ? g_counts[i] : 0;
    if (i < N_NODES) g_counts[i] = 0;
    int x = v;
#pragma unroll
    for (int o = 1; o < 32; o <<= 1) {
        int y = __shfl_up_sync(0xffffffffu, x, o);
        if (lane >= o) x += y;
    }
    if (lane == 31) ws[w] = x;
    __syncthreads();
    if (w == 0) {
        int y = (lane < 8) ? ws[lane] : 0;
#pragma unroll
        for (int o = 1; o < 32; o <<= 1) {
            int z = __shfl_up_sync(0xffffffffu, y, o);
            if (lane >= o) y += z;
        }
        if (lane < 8) ws[lane] = y;
    }
    __syncthreads();
    int pre = ((w > 0) ? ws[w - 1] : 0) + x - v;
    if (i <= N_NODES) g_offsets[i] = pre;
    if (i < N_NODES) g_cursor[i] = pre;
    if (t == 255) g_bsums[blockIdx.x] = ws[7];

    if (t == 0) {
        __threadfence();
        int k = atomicAdd(&g_tickA, 1);
        amLast = (k == SCAN_NBLK - 1);
        if (amLast) __threadfence();
    }
    __syncthreads();
    if (amLast) {
        int v2 = (t < SCAN_NBLK) ? g_bsums[t] : 0;
        int x2 = v2;
#pragma unroll
        for (int o = 1; o < 32; o <<= 1) {
            int y = __shfl_up_sync(0xffffffffu, x2, o);
            if (lane >= o) x2 += y;
        }
        __syncthreads();
        if (lane == 31) ws[w] = x2;
        __syncthreads();
        if (w == 0) {
            int y = (lane < 8) ? ws[lane] : 0;
#pragma unroll
            for (int o = 1; o < 32; o <<= 1) {
                int z = __shfl_up_sync(0xffffffffu, y, o);
                if (lane >= o) y += z;
            }
            if (lane < 8) ws[lane] = y;
        }
        __syncthreads();
        if (t < SCAN_NBLK) g_bpre[t] = ((w > 0) ? ws[w - 1] : 0) + x2 - v2;
        if (t == 0) g_tickA = 0;
    }
}

// ---------------- CSR: scatter ----------------
__global__ void scatter_kernel(const void* ei) {
    int is64 = probe_is64(ei);
    for (int e = blockIdx.x * blockDim.x + threadIdx.x; e < N_EDGES;
         e += gridDim.x * blockDim.x) {
        int s = load_index(ei, e, is64);
        int d = load_index(ei, (long long)N_EDGES + e, is64);
        int pos = g_bpre[d >> 8] + atomicAdd(&g_cursor[d], 1);
        g_srcidx[pos] = s;
    }
}

// ---------------- GIN aggregation (fp32 gather) -> bf16 hi/lo --------------
__global__ void agg_kernel(const float4* __restrict__ x4) {
    int node = blockIdx.x * 8 + (threadIdx.x >> 5);
    int lane = threadIdx.x & 31;
    if (node >= N_NODES) return;
    float4 acc = x4[node * 32 + lane];
    int e0 = g_offsets[node] + g_bpre[node >> 8];
    int e1 = g_offsets[node + 1] + g_bpre[(node + 1) >> 8];
    int e = e0;
    int n4 = e0 + ((e1 - e0) & ~3);
    for (; e < n4; e += 4) {
        int s0 = g_srcidx[e], s1 = g_srcidx[e + 1];
        int s2 = g_srcidx[e + 2], s3 = g_srcidx[e + 3];
        float4 v0 = x4[s0 * 32 + lane];
        float4 v1 = x4[s1 * 32 + lane];
        float4 v2 = x4[s2 * 32 + lane];
        float4 v3 = x4[s3 * 32 + lane];
        acc.x += v0.x + v1.x + v2.x + v3.x;
        acc.y += v0.y + v1.y + v2.y + v3.y;
        acc.z += v0.z + v1.z + v2.z + v3.z;
        acc.w += v0.w + v1.w + v2.w + v3.w;
    }
    for (; e < e1; e++) {
        int s = g_srcidx[e];
        float4 v = x4[s * 32 + lane];
        acc.x += v.x; acc.y += v.y; acc.z += v.z; acc.w += v.w;
    }
    float vv[4] = {acc.x, acc.y, acc.z, acc.w};
    unsigned short h[4], l[4];
#pragma unroll
    for (int i = 0; i < 4; i++) split_bf(vv[i], h[i], l[i]);
    uint2 hv = make_uint2((unsigned)h[0] | ((unsigned)h[1] << 16),
                          (unsigned)h[2] | ((unsigned)h[3] << 16));
    uint2 lv = make_uint2((unsigned)l[0] | ((unsigned)l[1] << 16),
                          (unsigned)l[2] | ((unsigned)l[3] << 16));
    ((uint2*)g_ahi)[node * 32 + lane] = hv;
    ((uint2*)g_alo)[node * 32 + lane] = lv;
}

// ---------------- fused dual GEMM (nn1 both layers) ------------------------
#define SA      0                 /* A/t1 tile: hi @ +0, lo @ +34816 */
#define ALO_OFF 34816
#define SWA_HI  69632
#define SWA_LO  104448
#define SWB_HI  139264
#define SWB_LO  174080
#define SBIAS1  208896
#define SBIAS2  209408
#define SBATCH  209920
#define GEMM_SMEM 210432

__device__ __forceinline__ void mainloop_128(uint32_t sbase, uint32_t wBase,
                                             uint32_t lOff, int m0, int n0,
                                             float c[2][8][4]) {
#pragma unroll
    for (int mh = 0; mh < 2; mh++)
#pragma unroll
        for (int j = 0; j < 8; j++)
#pragma unroll
            for (int q = 0; q < 4; q++) c[mh][j][q] = 0.f;

#pragma unroll 1
    for (int ks = 0; ks < 8; ks++) {
        uint32_t ah[2][4], al[2][4];
#pragma unroll
        for (int mh = 0; mh < 2; mh++) {
            uint32_t aa = sbase + SA + (uint32_t)(m0 + mh * 16) * 272 +
                          (uint32_t)ks * 32 + lOff;
            ldsm_x4(ah[mh], aa);
            ldsm_x4(al[mh], aa + ALO_OFF);
        }
#pragma unroll
        for (int nj = 0; nj < 4; nj++) {
            uint32_t bh[4], bl[4];
            uint32_t ba = sbase + wBase + (uint32_t)ks * 16 * 272 +
                          (uint32_t)(n0 + nj * 16) * 2 + lOff;
            ldsm_x4_t(bh, ba);
            ldsm_x4_t(bl, ba + ALO_OFF);
#pragma unroll
            for (int mh = 0; mh < 2; mh++) {
                mma_bf16(c[mh][2 * nj],     ah[mh], bh[0], bh[1]);
                mma_bf16(c[mh][2 * nj + 1], ah[mh], bh[2], bh[3]);
                mma_bf16(c[mh][2 * nj],     ah[mh], bl[0], bl[1]);
                mma_bf16(c[mh][2 * nj + 1], ah[mh], bl[2], bl[3]);
                mma_bf16(c[mh][2 * nj],     al[mh], bh[0], bh[1]);
                mma_bf16(c[mh][2 * nj + 1], al[mh], bh[2], bh[3]);
            }
        }
    }
}

__global__ __launch_bounds__(256, 1) void gemm_fused_kernel(
        const unsigned* __restrict__ Ahi, const unsigned* __restrict__ Alo,
        const float* __restrict__ W1a, const float* __restrict__ b1a,
        const float* __restrict__ W1b, const float* __restrict__ b1b,
        const void* __restrict__ batch, int M) {
    extern __shared__ char smem[];
    uint32_t sbase = smem_u32(smem);
    float* sBias1 = (float*)(smem + SBIAS1);
    float* sBias2 = (float*)(smem + SBIAS2);
    int* sB = (int*)(smem + SBATCH);
    int t = threadIdx.x;
    int lane = t & 31;
    int w = t >> 5;
    int wr = w >> 1, wc = w & 1;
    int m0 = wr * 32, n0 = wc * 64;
    int is64 = probe_is64(batch);

    {
        int tile0 = blockIdx.x;
        if (tile0 < NTILES) {
            int row0 = tile0 << 7;
            for (int idx = t; idx < 2048; idx += 256) {
                int r = idx >> 4, c4 = idx & 15;
                int gr = row0 + r;
                int ok = (gr < M) ? 16 : 0;
                int grc = ok ? gr : 0;
                cp_async16(sbase + SA + r * 272 + c4 * 16, Ahi + grc * 64 + c4 * 4, ok);
                cp_async16(sbase + SA + ALO_OFF + r * 272 + c4 * 16,
                           Alo + grc * 64 + c4 * 4, ok);
            }
        }
        CP_COMMIT();
    }

    for (int idx = t; idx < 128 * 128; idx += 256) {
        int k = idx >> 7, n = idx & 127;
        unsigned short h, l;
        split_bf(W1a[idx], h, l);
        *(unsigned short*)(smem + SWA_HI + (k * 136 + n) * 2) = h;
        *(unsigned short*)(smem + SWA_LO + (k * 136 + n) * 2) = l;
        split_bf(W1b[idx], h, l);
        *(unsigned short*)(smem + SWB_HI + (k * 136 + n) * 2) = h;
        *(unsigned short*)(smem + SWB_LO + (k * 136 + n) * 2) = l;
    }
    if (t < 128) { sBias1[t] = b1a[t]; sBias2[t] = b1b[t]; }

    int lrow = (lane & 7) + ((lane >> 3) & 1) * 8;
    int lcol = (lane >> 4) * 8;
    uint32_t lOff = (uint32_t)(lrow * 136 + lcol) * 2;
    int er = lane >> 2;
    int ec = 2 * (lane & 3);

    for (int tile = blockIdx.x; tile < NTILES; tile += gridDim.x) {
        int row0 = tile << 7;
        CP_WAIT0();
        __syncthreads();

        float c[2][8][4];
        mainloop_128(sbase, SWA_HI, lOff, m0, n0, c);
        __syncthreads();

#pragma unroll
        for (int mh = 0; mh < 2; mh++)
#pragma unroll
            for (int j = 0; j < 8; j++) {
                int n = n0 + j * 8 + ec;
                float b0 = sBias1[n], b1 = sBias1[n + 1];
                float* cc = c[mh][j];
                int r0 = m0 + mh * 16 + er;
                unsigned short h0, l0, h1, l1;
                split_bf(fmaxf(cc[0] + b0, 0.f), h0, l0);
                split_bf(fmaxf(cc[1] + b1, 0.f), h1, l1);
                *(unsigned*)(smem + SA + r0 * 272 + n * 2) =
                    (unsigned)h0 | ((unsigned)h1 << 16);
                *(unsigned*)(smem + SA + ALO_OFF + r0 * 272 + n * 2) =
                    (unsigned)l0 | ((unsigned)l1 << 16);
                split_bf(fmaxf(cc[2] + b0, 0.f), h0, l0);
                split_bf(fmaxf(cc[3] + b1, 0.f), h1, l1);
                *(unsigned*)(smem + SA + (r0 + 8) * 272 + n * 2) =
                    (unsigned)h0 | ((unsigned)h1 << 16);
                *(unsigned*)(smem + SA + ALO_OFF + (r0 + 8) * 272 + n * 2) =
                    (unsigned)l0 | ((unsigned)l1 << 16);
            }
        __syncthreads();

        mainloop_128(sbase, SWB_HI, lOff, m0, n0, c);
        __syncthreads();

        float* sV = (float*)(smem + SA);
#pragma unroll
        for (int mh = 0; mh < 2; mh++)
#pragma unroll
            for (int j = 0; j < 8; j++) {
                int n = n0 + j * 8 + ec;
                int rr = m0 + mh * 16 + er;
                float b0 = sBias2[n], b1 = sBias2[n + 1];
                float* cc = c[mh][j];
                *(float2*)&sV[rr * 132 + n] =
                    make_float2(fmaxf(cc[0] + b0, 0.f), fmaxf(cc[1] + b1, 0.f));
                *(float2*)&sV[(rr + 8) * 132 + n] =
                    make_float2(fmaxf(cc[2] + b0, 0.f), fmaxf(cc[3] + b1, 0.f));
            }
        if (t < 128) {
            int gr = row0 + t;
            sB[t] = (gr < M) ? load_index(batch, gr, is64) : -1;
        }
        __syncthreads();

        if (t < 128) {
            float s = 0.f, q = 0.f, run = 0.f;
            int cur = sB[0];
            for (int r = 0; r < 128; r++) {
                int b = sB[r];
                if (b != cur) {
                    if (cur >= 0) atomicAdd(&g_gsum[cur * NF + t], run);
                    run = 0.f;
                    cur = b;
                }
                if (b >= 0) {
                    float v = sV[r * 132 + t];
                    run += v;
                    s += v;
                    q += v * v;
                }
            }
            if (cur >= 0) atomicAdd(&g_gsum[cur * NF + t], run);
            atomicAdd(&g_stats[t], s);
            atomicAdd(&g_stats[128 + t], q);
        }
        __syncthreads();

        {
            int nt = tile + gridDim.x;
            if (nt < NTILES) {
                int row0n = nt << 7;
                for (int idx = t; idx < 2048; idx += 256) {
                    int r = idx >> 4, c4 = idx & 15;
                    int gr = row0n + r;
                    int ok = (gr < M) ? 16 : 0;
                    int grc = ok ? gr : 0;
                    cp_async16(sbase + SA + r * 272 + c4 * 16,
                               Ahi + grc * 64 + c4 * 4, ok);
                    cp_async16(sbase + SA + ALO_OFF + r * 272 + c4 * 16,
                               Alo + grc * 64 + c4 * 4, ok);
                }
            }
            CP_COMMIT();
        }
    }
}

// ---------------- fused: BN-affine pool + recurrence + output MLP ----------
// One graph per block, 512 threads: thread = (col c in [0,128), quarter q).
// Recurrence weights in REGISTERS as packed f32x2 pairs; inner loop uses
// Blackwell packed fma.rn.f32x2 (2x scalar-FFMA throughput). cat reads are
// broadcast 8-byte LDS (conflict-free).
__global__ __launch_bounds__(512, 1) void recur_mlp_kernel(
        const void* __restrict__ batch,
        const float* __restrict__ gamma, const float* __restrict__ beta,
        const float* __restrict__ Wl1, const float* __restrict__ bl1,
        const float* __restrict__ Wl2, const float* __restrict__ bl2,
        const float* __restrict__ Wm1, const float* __restrict__ bm1,
        const float* __restrict__ Wm2, const float* __restrict__ bm2,
        float* __restrict__ out) {
    __shared__ float cat[256];     // [xg(128) | h(128)] for this graph
    __shared__ float part[512];
    __shared__ float hid[DIM];
    __shared__ int se[3];          // [start, end, lastflag]
    int t = threadIdx.x;
    int g = blockIdx.x;
    int c = t & 127;
    int q = t >> 7;                // 0..3 (k-quarter)
    int is64 = probe_is64(batch);

    if (t < 2) {
        int target = g + t;
        int lo = 0, hi = N_NODES;
        while (lo < hi) {
            int mid = (lo + hi) >> 1;
            int b = load_index(batch, mid, is64);
            if (b < target) lo = mid + 1; else hi = mid;
        }
        se[t] = lo;
    }

    // recurrence weights -> registers as packed f32x2 pairs (coalesced over c)
    unsigned long long wp[32];
    {
        const float* Wsrc = (c < 64) ? (Wl2 + c) : (Wl1 + (c - 64));
        int kbase = q * 64;
#pragma unroll
        for (int i = 0; i < 32; i++) {
            float w0 = Wsrc[(kbase + 2 * i) * 64];
            float w1 = Wsrc[(kbase + 2 * i + 1) * 64];
            wp[i] = pack_f32x2(w0, w1);
        }
    }
    float bias = 0.f;
    if (t < 128) bias = (t < 64) ? bl2[t] : bl1[t - 64];

    // stats + own gsum (read, then ticketed zeroing)
    float ss = 0.f, sq = 0.f, gsv = 0.f;
    if (t < 128) {
        ss = g_stats[t];
        sq = g_stats[128 + t];
        gsv = g_gsum[g * NF + t];
        g_gsum[g * NF + t] = 0.f;
    }
    __syncthreads();
    if (t == 0) {
        __threadfence();
        int k = atomicAdd(&g_tickR, 1);
        se[2] = (k == N_GRAPHS - 1);
    }
    __syncthreads();
    if (se[2]) {
        if (t < 256) g_stats[t] = 0.f;
        if (t == 0) g_tickR = 0;
    }

    if (t < 128) {
        int cnt = se[1] - se[0];
        float mu = ss / (float)N_NODES;
        float var = sq / (float)N_NODES - mu * mu;
        float val = 0.f;
        if (cnt > 0) {
            float m = gsv / (float)cnt;
            val = gamma[t] * (m - mu) * rsqrtf(var + BN_EPS) + beta[t];
        }
        cat[t] = val;            // xg half (constant)
        cat[128 + t] = val;      // h init = xg
    }
    __syncthreads();

    for (int it = 0; it < N_ITERS; it++) {
        const float* ck = &cat[q * 64];
        unsigned long long acc0 = pack_f32x2(0.f, 0.f);
        unsigned long long acc1 = pack_f32x2(0.f, 0.f);
#pragma unroll
        for (int i = 0; i < 32; i += 2) {
            unsigned long long c0 = *(const unsigned long long*)&ck[2 * i];
            unsigned long long c1 = *(const unsigned long long*)&ck[2 * i + 2];
            asm("fma.rn.f32x2 %0, %1, %2, %0;" : "+l"(acc0) : "l"(wp[i]), "l"(c0));
            asm("fma.rn.f32x2 %0, %1, %2, %0;" : "+l"(acc1) : "l"(wp[i + 1]), "l"(c1));
        }
        float l0, h0, l1, h1;
        unpack_f32x2(acc0, l0, h0);
        unpack_f32x2(acc1, l1, h1);
        part[t] = (l0 + h0) + (l1 + h1);
        __syncthreads();
        if (t < 128) {
            float o = part[t] + part[t + 128] + part[t + 256] + part[t + 384] + bias;
            float v = (t < 64) ? tanhf(o) : (1.0f / (1.0f + expf(-o)));
            cat[128 + t] = v;
        }
        __syncthreads();
    }

    // output MLP for this graph
    if (t < DIM) {
        float a = bm1[t];
        const float* h = &cat[128];
#pragma unroll 8
        for (int k = 0; k < NF; k++) a += h[k] * Wm1[k * DIM + t];
        hid[t] = fmaxf(a, 0.f);
    }
    __syncthreads();
    if (t < N_OUT) {
        float a = bm2[t];
        for (int k = 0; k < DIM; k++) a += hid[k] * Wm2[k * N_OUT + t];
        out[g * N_OUT + t] = a;
    }
}

// ---------------- host ----------------
extern "C" void kernel_launch(void* const* d_in, const int* in_sizes, int n_in,
                              void* d_out, int out_size) {
    const float* x     = (const float*)d_in[0];
    const void*  ei    = d_in[1];
    const void*  batch = d_in[2];
    const float* W1a = (const float*)d_in[3];
    const float* b1a = (const float*)d_in[4];
    const float* W1b = (const float*)d_in[5];
    const float* b1b = (const float*)d_in[6];
    const float* gamma = (const float*)d_in[7];
    const float* beta  = (const float*)d_in[8];
    const float* Wl1 = (const float*)d_in[9];
    const float* bl1 = (const float*)d_in[10];
    const float* Wl2 = (const float*)d_in[11];
    const float* bl2 = (const float*)d_in[12];
    const float* Wm1 = (const float*)d_in[13];
    const float* bm1 = (const float*)d_in[14];
    const float* Wm2 = (const float*)d_in[15];
    const float* bm2 = (const float*)d_in[16];
    float* out = (float*)d_out;

    void *p_ahi, *p_alo;
    cudaGetSymbolAddress(&p_ahi, g_ahi);
    cudaGetSymbolAddress(&p_alo, g_alo);

    cudaFuncSetAttribute(gemm_fused_kernel,
                         cudaFuncAttributeMaxDynamicSharedMemorySize, GEMM_SMEM);

    count_kernel<<<512, 256>>>(ei);
    scanAB_kernel<<<SCAN_NBLK, 256>>>();
    scatter_kernel<<<512, 256>>>(ei);
    agg_kernel<<<(N_NODES + 7) / 8, 256>>>((const float4*)x);
    gemm_fused_kernel<<<148, 256, GEMM_SMEM>>>(
        (const unsigned*)p_ahi, (const unsigned*)p_alo,
        W1a, b1a, W1b, b1b, batch, N_NODES);
    recur_mlp_kernel<<<N_GRAPHS, 512>>>(
        batch, gamma, beta, Wl1, bl1, Wl2, bl2, Wm1, bm1, Wm2, bm2, out);
}

// round 15
// speedup vs baseline: 1.4692x; 1.1862x over previous
#include <cuda_runtime.h>
#include <cuda_fp16.h>
#include <math.h>
#include <stdint.h>

#define N_NODES  50000
#define N_EDGES  600000
#define NF       128
#define N_GRAPHS 256
#define DIM      95
#define N_OUT    12
#define N_ITERS  10
#define BN_EPS   1e-5f
#define SCAN_NBLK 196
#define NTILES   391             // ceil(50000/128)

// ---------------- scratch (zero-initialized at load; self-cleaning) --------
__device__ unsigned g_a16[N_NODES * 64];   // fp16x2 packed: (x+agg)
__device__ int   g_counts[N_NODES];        // zeroed by scanAB after use
__device__ int   g_offsets[N_NODES + 1];   // block-local prefixes
__device__ int   g_cursor[N_NODES];
__device__ int   g_srcidx[N_EDGES];
__device__ int   g_bsums[SCAN_NBLK];
__device__ int   g_bpre[SCAN_NBLK];
__device__ float g_stats[2 * NF];          // zeroed by recur last block
__device__ float g_gsum[N_GRAPHS * NF];    // zeroed by its recur block
__device__ int   g_tickA;                  // self-resetting tickets
__device__ int   g_tickR;

// ---------------- helpers ----------------
__device__ __forceinline__ uint32_t smem_u32(const void* p) {
    uint32_t a;
    asm("{ .reg .u64 t; cvta.to.shared.u64 t, %1; cvt.u32.u64 %0, t; }" : "=r"(a) : "l"(p));
    return a;
}
__device__ __forceinline__ void ldsm_x4(uint32_t* r, uint32_t addr) {
    asm volatile("ldmatrix.sync.aligned.m8n8.x4.shared.b16 {%0,%1,%2,%3}, [%4];"
        : "=r"(r[0]), "=r"(r[1]), "=r"(r[2]), "=r"(r[3]) : "r"(addr));
}
__device__ __forceinline__ void ldsm_x4_t(uint32_t* r, uint32_t addr) {
    asm volatile("ldmatrix.sync.aligned.m8n8.x4.trans.shared.b16 {%0,%1,%2,%3}, [%4];"
        : "=r"(r[0]), "=r"(r[1]), "=r"(r[2]), "=r"(r[3]) : "r"(addr));
}
__device__ __forceinline__ void mma_f16(float* c, const uint32_t* a,
                                        uint32_t b0, uint32_t b1) {
    asm volatile("mma.sync.aligned.m16n8k16.row.col.f32.f16.f16.f32 "
        "{%0,%1,%2,%3}, {%4,%5,%6,%7}, {%8,%9}, {%0,%1,%2,%3};"
        : "+f"(c[0]), "+f"(c[1]), "+f"(c[2]), "+f"(c[3])
        : "r"(a[0]), "r"(a[1]), "r"(a[2]), "r"(a[3]), "r"(b0), "r"(b1));
}
__device__ __forceinline__ void cp_async16(uint32_t dst, const void* src, int srcsz) {
    asm volatile("cp.async.cg.shared.global [%0], [%1], 16, %2;"
        :: "r"(dst), "l"(src), "r"(srcsz) : "memory");
}
#define CP_COMMIT() asm volatile("cp.async.commit_group;" ::: "memory")
#define CP_WAIT0()  asm volatile("cp.async.wait_group 0;" ::: "memory")
__device__ __forceinline__ int load_index(const void* p, long long i, int is64) {
    if (is64) return (int)((const long long*)p)[i];
    return ((const int*)p)[i];
}
__device__ __forceinline__ int probe_is64(const void* p) {
    const int* w32 = (const int*)p;
    int bad = 0;
    for (int j = threadIdx.x; j < 1024; j += blockDim.x)
        if (w32[2 * j + 1] != 0) bad = 1;
    return !__syncthreads_or(bad);
}
__device__ __forceinline__ unsigned long long pack_f32x2(float lo, float hi) {
    unsigned long long u;
    asm("mov.b64 %0, {%1, %2};" : "=l"(u) : "f"(lo), "f"(hi));
    return u;
}
__device__ __forceinline__ void unpack_f32x2(unsigned long long u, float& lo, float& hi) {
    asm("mov.b64 {%0, %1}, %2;" : "=f"(lo), "=f"(hi) : "l"(u));
}
__device__ __forceinline__ unsigned pack_h2(float a, float b) {
    __half ha = __float2half_rn(a), hb = __float2half_rn(b);
    return (unsigned)__half_as_ushort(ha) | ((unsigned)__half_as_ushort(hb) << 16);
}

// ---------------- CSR: count ----------------
__global__ void count_kernel(const void* ei) {
    int is64 = probe_is64(ei);
    for (int e = blockIdx.x * blockDim.x + threadIdx.x; e < N_EDGES;
         e += gridDim.x * blockDim.x) {
        int d = load_index(ei, (long long)N_EDGES + e, is64);
        atomicAdd(&g_counts[d], 1);
    }
}

// ---------------- fused scan ----------------
__global__ void scanAB_kernel() {
    __shared__ int ws[8];
    __shared__ int amLast;
    int t = threadIdx.x, lane = t & 31, w = t >> 5;
    int i = blockIdx.x * 256 + t;
    int v = (i < N_NODES) ? g_counts[i] : 0;
    if (i < N_NODES) g_counts[i] = 0;
    int x = v;
#pragma unroll
    for (int o = 1; o < 32; o <<= 1) {
        int y = __shfl_up_sync(0xffffffffu, x, o);
        if (lane >= o) x += y;
    }
    if (lane == 31) ws[w] = x;
    __syncthreads();
    if (w == 0) {
        int y = (lane < 8) ? ws[lane] : 0;
#pragma unroll
        for (int o = 1; o < 32; o <<= 1) {
            int z = __shfl_up_sync(0xffffffffu, y, o);
            if (lane >= o) y += z;
        }
        if (lane < 8) ws[lane] = y;
    }
    __syncthreads();
    int pre = ((w > 0) ? ws[w - 1] : 0) + x - v;
    if (i <= N_NODES) g_offsets[i] = pre;
    if (i < N_NODES) g_cursor[i] = pre;
    if (t == 255) g_bsums[blockIdx.x] = ws[7];

    if (t == 0) {
        __threadfence();
        int k = atomicAdd(&g_tickA, 1);
        amLast = (k == SCAN_NBLK - 1);
        if (amLast) __threadfence();
    }
    __syncthreads();
    if (amLast) {
        int v2 = (t < SCAN_NBLK) ? g_bsums[t] : 0;
        int x2 = v2;
#pragma unroll
        for (int o = 1; o < 32; o <<= 1) {
            int y = __shfl_up_sync(0xffffffffu, x2, o);
            if (lane >= o) x2 += y;
        }
        __syncthreads();
        if (lane == 31) ws[w] = x2;
        __syncthreads();
        if (w == 0) {
            int y = (lane < 8) ? ws[lane] : 0;
#pragma unroll
            for (int o = 1; o < 32; o <<= 1) {
                int z = __shfl_up_sync(0xffffffffu, y, o);
                if (lane >= o) y += z;
            }
            if (lane < 8) ws[lane] = y;
        }
        __syncthreads();
        if (t < SCAN_NBLK) g_bpre[t] = ((w > 0) ? ws[w - 1] : 0) + x2 - v2;
        if (t == 0) g_tickA = 0;
    }
}

// ---------------- CSR: scatter ----------------
__global__ void scatter_kernel(const void* ei) {
    int is64 = probe_is64(ei);
    for (int e = blockIdx.x * blockDim.x + threadIdx.x; e < N_EDGES;
         e += gridDim.x * blockDim.x) {
        int s = load_index(ei, e, is64);
        int d = load_index(ei, (long long)N_EDGES + e, is64);
        int pos = g_bpre[d >> 8] + atomicAdd(&g_cursor[d], 1);
        g_srcidx[pos] = s;
    }
}

// ---------------- GIN aggregation (fp32 gather) -> fp16 packed -------------
__global__ void agg_kernel(const float4* __restrict__ x4) {
    int node = blockIdx.x * 8 + (threadIdx.x >> 5);
    int lane = threadIdx.x & 31;
    if (node >= N_NODES) return;
    float4 acc = x4[node * 32 + lane];
    int e0 = g_offsets[node] + g_bpre[node >> 8];
    int e1 = g_offsets[node + 1] + g_bpre[(node + 1) >> 8];
    int e = e0;
    int n4 = e0 + ((e1 - e0) & ~3);
    for (; e < n4; e += 4) {
        int s0 = g_srcidx[e], s1 = g_srcidx[e + 1];
        int s2 = g_srcidx[e + 2], s3 = g_srcidx[e + 3];
        float4 v0 = x4[s0 * 32 + lane];
        float4 v1 = x4[s1 * 32 + lane];
        float4 v2 = x4[s2 * 32 + lane];
        float4 v3 = x4[s3 * 32 + lane];
        acc.x += v0.x + v1.x + v2.x + v3.x;
        acc.y += v0.y + v1.y + v2.y + v3.y;
        acc.z += v0.z + v1.z + v2.z + v3.z;
        acc.w += v0.w + v1.w + v2.w + v3.w;
    }
    for (; e < e1; e++) {
        int s = g_srcidx[e];
        float4 v = x4[s * 32 + lane];
        acc.x += v.x; acc.y += v.y; acc.z += v.z; acc.w += v.w;
    }
    uint2 pv = make_uint2(pack_h2(acc.x, acc.y), pack_h2(acc.z, acc.w));
    ((uint2*)g_a16)[node * 32 + lane] = pv;
}

// ---------------- fused dual GEMM (nn1 both layers), single fp16 -----------
// x1 = relu(relu(A@W1a + b1a)@W1b + b1b), everything fp16 in / fp32 accum.
// t1 AND x1 live only in smem (fp16 in the A region). Epilogue 2: fused BN
// stats + per-graph pooling sums. 104KB smem -> 2 blocks/SM, grid 296.
#define SA      0                 /* A/t1/x1 tile: 128 x 272B = 34816 */
#define SWA     34816
#define SWB     69632
#define SBIAS1  104448
#define SBIAS2  104960
#define SBATCH  105472
#define GEMM_SMEM 105984

__device__ __forceinline__ void mainloop_f16(uint32_t sbase, uint32_t wBase,
                                             uint32_t lOff, int m0, int n0,
                                             float c[2][8][4]) {
#pragma unroll
    for (int mh = 0; mh < 2; mh++)
#pragma unroll
        for (int j = 0; j < 8; j++)
#pragma unroll
            for (int q = 0; q < 4; q++) c[mh][j][q] = 0.f;

#pragma unroll
    for (int ks = 0; ks < 8; ks++) {
        uint32_t a[2][4];
#pragma unroll
        for (int mh = 0; mh < 2; mh++)
            ldsm_x4(a[mh], sbase + SA + (uint32_t)(m0 + mh * 16) * 272 +
                           (uint32_t)ks * 32 + lOff);
#pragma unroll
        for (int nj = 0; nj < 4; nj++) {
            uint32_t b[4];
            ldsm_x4_t(b, sbase + wBase + (uint32_t)ks * 16 * 272 +
                         (uint32_t)(n0 + nj * 16) * 2 + lOff);
#pragma unroll
            for (int mh = 0; mh < 2; mh++) {
                mma_f16(c[mh][2 * nj],     a[mh], b[0], b[1]);
                mma_f16(c[mh][2 * nj + 1], a[mh], b[2], b[3]);
            }
        }
    }
}

__global__ __launch_bounds__(256, 2) void gemm_fused_kernel(
        const unsigned* __restrict__ A16,
        const float* __restrict__ W1a, const float* __restrict__ b1a,
        const float* __restrict__ W1b, const float* __restrict__ b1b,
        const void* __restrict__ batch, int M) {
    extern __shared__ char smem[];
    uint32_t sbase = smem_u32(smem);
    float* sBias1 = (float*)(smem + SBIAS1);
    float* sBias2 = (float*)(smem + SBIAS2);
    int* sB = (int*)(smem + SBATCH);
    int t = threadIdx.x;
    int lane = t & 31;
    int w = t >> 5;
    int wr = w >> 1, wc = w & 1;
    int m0 = wr * 32, n0 = wc * 64;
    int is64 = probe_is64(batch);

    // prologue: prefetch first tile (each row: 64 uints = 16 chunks of 16B)
    {
        int tile0 = blockIdx.x;
        if (tile0 < NTILES) {
            int row0 = tile0 << 7;
            for (int idx = t; idx < 2048; idx += 256) {
                int r = idx >> 4, c4 = idx & 15;
                int gr = row0 + r;
                int ok = (gr < M) ? 16 : 0;
                int grc = ok ? gr : 0;
                cp_async16(sbase + SA + r * 272 + c4 * 16, A16 + grc * 64 + c4 * 4, ok);
            }
        }
        CP_COMMIT();
    }

    // weights -> smem fp16, once
    for (int idx = t; idx < 128 * 128; idx += 256) {
        int k = idx >> 7, n = idx & 127;
        *(unsigned short*)(smem + SWA + (k * 136 + n) * 2) =
            __half_as_ushort(__float2half_rn(W1a[idx]));
        *(unsigned short*)(smem + SWB + (k * 136 + n) * 2) =
            __half_as_ushort(__float2half_rn(W1b[idx]));
    }
    if (t < 128) { sBias1[t] = b1a[t]; sBias2[t] = b1b[t]; }

    int lrow = (lane & 7) + ((lane >> 3) & 1) * 8;
    int lcol = (lane >> 4) * 8;
    uint32_t lOff = (uint32_t)(lrow * 136 + lcol) * 2;
    int er = lane >> 2;
    int ec = 2 * (lane & 3);

    for (int tile = blockIdx.x; tile < NTILES; tile += gridDim.x) {
        int row0 = tile << 7;
        CP_WAIT0();
        __syncthreads();

        float c[2][8][4];
        // ---- GEMM 1: A @ W1a ----
        mainloop_f16(sbase, SWA, lOff, m0, n0, c);
        __syncthreads();

        // epilogue 1: bias+relu -> fp16 t1 back into SA
#pragma unroll
        for (int mh = 0; mh < 2; mh++)
#pragma unroll
            for (int j = 0; j < 8; j++) {
                int n = n0 + j * 8 + ec;
                float b0 = sBias1[n], b1 = sBias1[n + 1];
                float* cc = c[mh][j];
                int r0 = m0 + mh * 16 + er;
                *(unsigned*)(smem + SA + r0 * 272 + n * 2) =
                    pack_h2(fmaxf(cc[0] + b0, 0.f), fmaxf(cc[1] + b1, 0.f));
                *(unsigned*)(smem + SA + (r0 + 8) * 272 + n * 2) =
                    pack_h2(fmaxf(cc[2] + b0, 0.f), fmaxf(cc[3] + b1, 0.f));
            }
        __syncthreads();

        // ---- GEMM 2: t1 @ W1b ----
        mainloop_f16(sbase, SWB, lOff, m0, n0, c);
        __syncthreads();

        // epilogue 2: bias+relu -> fp16 x1 into SA
#pragma unroll
        for (int mh = 0; mh < 2; mh++)
#pragma unroll
            for (int j = 0; j < 8; j++) {
                int n = n0 + j * 8 + ec;
                float b0 = sBias2[n], b1 = sBias2[n + 1];
                float* cc = c[mh][j];
                int r0 = m0 + mh * 16 + er;
                *(unsigned*)(smem + SA + r0 * 272 + n * 2) =
                    pack_h2(fmaxf(cc[0] + b0, 0.f), fmaxf(cc[1] + b1, 0.f));
                *(unsigned*)(smem + SA + (r0 + 8) * 272 + n * 2) =
                    pack_h2(fmaxf(cc[2] + b0, 0.f), fmaxf(cc[3] + b1, 0.f));
            }
        if (t < 128) {
            int gr = row0 + t;
            sB[t] = (gr < M) ? load_index(batch, gr, is64) : -1;
        }
        __syncthreads();

        // fused BN stats + per-graph pooling sums (read x1 fp16 from SA)
        if (t < 128) {
            float s = 0.f, q = 0.f, run = 0.f;
            int cur = sB[0];
            for (int r = 0; r < 128; r++) {
                int b = sB[r];
                if (b != cur) {
                    if (cur >= 0) atomicAdd(&g_gsum[cur * NF + t], run);
                    run = 0.f;
                    cur = b;
                }
                if (b >= 0) {
                    float v = __half2float(
                        *(const __half*)(smem + SA + r * 272 + t * 2));
                    run += v;
                    s += v;
                    q += v * v;
                }
            }
            if (cur >= 0) atomicAdd(&g_gsum[cur * NF + t], run);
            atomicAdd(&g_stats[t], s);
            atomicAdd(&g_stats[128 + t], q);
        }
        __syncthreads();

        // prefetch next tile
        {
            int nt = tile + gridDim.x;
            if (nt < NTILES) {
                int row0n = nt << 7;
                for (int idx = t; idx < 2048; idx += 256) {
                    int r = idx >> 4, c4 = idx & 15;
                    int gr = row0n + r;
                    int ok = (gr < M) ? 16 : 0;
                    int grc = ok ? gr : 0;
                    cp_async16(sbase + SA + r * 272 + c4 * 16,
                               A16 + grc * 64 + c4 * 4, ok);
                }
            }
            CP_COMMIT();
        }
    }
}

// ---------------- fused: BN-affine pool + recurrence + output MLP ----------
__global__ __launch_bounds__(512, 1) void recur_mlp_kernel(
        const void* __restrict__ batch,
        const float* __restrict__ gamma, const float* __restrict__ beta,
        const float* __restrict__ Wl1, const float* __restrict__ bl1,
        const float* __restrict__ Wl2, const float* __restrict__ bl2,
        const float* __restrict__ Wm1, const float* __restrict__ bm1,
        const float* __restrict__ Wm2, const float* __restrict__ bm2,
        float* __restrict__ out) {
    __shared__ float cat[256];
    __shared__ float part[512];
    __shared__ float hid[DIM];
    __shared__ int se[3];
    int t = threadIdx.x;
    int g = blockIdx.x;
    int c = t & 127;
    int q = t >> 7;
    int is64 = probe_is64(batch);

    if (t < 2) {
        int target = g + t;
        int lo = 0, hi = N_NODES;
        while (lo < hi) {
            int mid = (lo + hi) >> 1;
            int b = load_index(batch, mid, is64);
            if (b < target) lo = mid + 1; else hi = mid;
        }
        se[t] = lo;
    }

    unsigned long long wp[32];
    {
        const float* Wsrc = (c < 64) ? (Wl2 + c) : (Wl1 + (c - 64));
        int kbase = q * 64;
#pragma unroll
        for (int i = 0; i < 32; i++) {
            float w0 = Wsrc[(kbase + 2 * i) * 64];
            float w1 = Wsrc[(kbase + 2 * i + 1) * 64];
            wp[i] = pack_f32x2(w0, w1);
        }
    }
    float bias = 0.f;
    if (t < 128) bias = (t < 64) ? bl2[t] : bl1[t - 64];

    float ss = 0.f, sq = 0.f, gsv = 0.f;
    if (t < 128) {
        ss = g_stats[t];
        sq = g_stats[128 + t];
        gsv = g_gsum[g * NF + t];
        g_gsum[g * NF + t] = 0.f;
    }
    __syncthreads();
    if (t == 0) {
        __threadfence();
        int k = atomicAdd(&g_tickR, 1);
        se[2] = (k == N_GRAPHS - 1);
    }
    __syncthreads();
    if (se[2]) {
        if (t < 256) g_stats[t] = 0.f;
        if (t == 0) g_tickR = 0;
    }

    if (t < 128) {
        int cnt = se[1] - se[0];
        float mu = ss / (float)N_NODES;
        float var = sq / (float)N_NODES - mu * mu;
        float val = 0.f;
        if (cnt > 0) {
            float m = gsv / (float)cnt;
            val = gamma[t] * (m - mu) * rsqrtf(var + BN_EPS) + beta[t];
        }
        cat[t] = val;
        cat[128 + t] = val;
    }
    __syncthreads();

    for (int it = 0; it < N_ITERS; it++) {
        const float* ck = &cat[q * 64];
        unsigned long long acc0 = pack_f32x2(0.f, 0.f);
        unsigned long long acc1 = pack_f32x2(0.f, 0.f);
#pragma unroll
        for (int i = 0; i < 32; i += 2) {
            unsigned long long c0 = *(const unsigned long long*)&ck[2 * i];
            unsigned long long c1 = *(const unsigned long long*)&ck[2 * i + 2];
            asm("fma.rn.f32x2 %0, %1, %2, %0;" : "+l"(acc0) : "l"(wp[i]), "l"(c0));
            asm("fma.rn.f32x2 %0, %1, %2, %0;" : "+l"(acc1) : "l"(wp[i + 1]), "l"(c1));
        }
        float l0, h0, l1, h1;
        unpack_f32x2(acc0, l0, h0);
        unpack_f32x2(acc1, l1, h1);
        part[t] = (l0 + h0) + (l1 + h1);
        __syncthreads();
        if (t < 128) {
            float o = part[t] + part[t + 128] + part[t + 256] + part[t + 384] + bias;
            float v = (t < 64) ? tanhf(o) : (1.0f / (1.0f + expf(-o)));
            cat[128 + t] = v;
        }
        __syncthreads();
    }

    if (t < DIM) {
        float a = bm1[t];
        const float* h = &cat[128];
#pragma unroll 8
        for (int k = 0; k < NF; k++) a += h[k] * Wm1[k * DIM + t];
        hid[t] = fmaxf(a, 0.f);
    }
    __syncthreads();
    if (t < N_OUT) {
        float a = bm2[t];
        for (int k = 0; k < DIM; k++) a += hid[k] * Wm2[k * N_OUT + t];
        out[g * N_OUT + t] = a;
    }
}

// ---------------- host ----------------
extern "C" void kernel_launch(void* const* d_in, const int* in_sizes, int n_in,
                              void* d_out, int out_size) {
    const float* x     = (const float*)d_in[0];
    const void*  ei    = d_in[1];
    const void*  batch = d_in[2];
    const float* W1a = (const float*)d_in[3];
    const float* b1a = (const float*)d_in[4];
    const float* W1b = (const float*)d_in[5];
    const float* b1b = (const float*)d_in[6];
    const float* gamma = (const float*)d_in[7];
    const float* beta  = (const float*)d_in[8];
    const float* Wl1 = (const float*)d_in[9];
    const float* bl1 = (const float*)d_in[10];
    const float* Wl2 = (const float*)d_in[11];
    const float* bl2 = (const float*)d_in[12];
    const float* Wm1 = (const float*)d_in[13];
    const float* bm1 = (const float*)d_in[14];
    const float* Wm2 = (const float*)d_in[15];
    const float* bm2 = (const float*)d_in[16];
    float* out = (float*)d_out;

    void* p_a16;
    cudaGetSymbolAddress(&p_a16, g_a16);

    cudaFuncSetAttribute(gemm_fused_kernel,
                         cudaFuncAttributeMaxDynamicSharedMemorySize, GEMM_SMEM);

    count_kernel<<<512, 256>>>(ei);
    scanAB_kernel<<<SCAN_NBLK, 256>>>();
    scatter_kernel<<<512, 256>>>(ei);
    agg_kernel<<<(N_NODES + 7) / 8, 256>>>((const float4*)x);
    gemm_fused_kernel<<<296, 256, GEMM_SMEM>>>(
        (const unsigned*)p_a16, W1a, b1a, W1b, b1b, batch, N_NODES);
    recur_mlp_kernel<<<N_GRAPHS, 512>>>(
        batch, gamma, beta, Wl1, bl1, Wl2, bl2, Wm1, bm1, Wm2, bm2, out);
}